// round 4
// baseline (speedup 1.0000x reference)
#include <cuda_runtime.h>
#include <math.h>
#include <stdint.h>

// ---------------- static scratch (no allocations allowed) ----------------
#define NMAX   131072
#define TMAX   1700000

__device__ float g_msgs[(size_t)TMAX * 64];
__device__ int   g_colidx[TMAX];
__device__ int   g_counts[NMAX];
__device__ int   g_rowptr[NMAX + 1];
__device__ int   g_cursor[NMAX];
__device__ float g_hA[(size_t)NMAX * 64];
__device__ float g_hB[(size_t)NMAX * 64];
__device__ float g_maxmsg[(size_t)NMAX * 64];
__device__ int   g_bounds[257];
__device__ float g_agg[256 * 64];

// pre-converted tf32 weights
__device__ unsigned g_tfWi1[64 * 64],   g_tfWo1[64 * 64];
__device__ unsigned g_tfWi2[128 * 128], g_tfWo2[128 * 128];
__device__ unsigned g_tfWi3[192 * 192], g_tfWo3[192 * 192];
__device__ unsigned g_tfuWi[128 * 128], g_tfuWo[128 * 64];

// ---------------- math helpers ----------------
__device__ __forceinline__ float mishf(float x) {
    if (x > 20.f) return x;
    float e = __expf(x);
    float n = e * (e + 2.f);
    return x * (n / (n + 2.f));
}

__device__ __forceinline__ void smax_upd(float& m, float& s, float v) {
    if (v > m) { s = s * __expf(12.f * (m - v)) + 1.f; m = v; }
    else       { s += __expf(12.f * (v - m)); }
}

__device__ __forceinline__ unsigned f2tf(float x) {
    unsigned r;
    asm("cvt.rna.tf32.f32 %0, %1;" : "=r"(r) : "f"(x));
    return r;
}

__device__ __forceinline__ void mma8(float* c, unsigned a0, unsigned a1, unsigned a2, unsigned a3,
                                     unsigned b0, unsigned b1) {
    asm volatile(
        "mma.sync.aligned.m16n8k8.row.col.f32.tf32.tf32.f32 "
        "{%0,%1,%2,%3}, {%4,%5,%6,%7}, {%8,%9}, {%0,%1,%2,%3};\n"
        : "+f"(c[0]), "+f"(c[1]), "+f"(c[2]), "+f"(c[3])
        : "r"(a0), "r"(a1), "r"(a2), "r"(a3), "r"(b0), "r"(b1));
}

// ---------------- weight pre-conversion ----------------
__global__ void conv_kernel(const float* __restrict__ src, int sel, int n) {
    unsigned* dst =
        (sel == 0) ? g_tfWi1 : (sel == 1) ? g_tfWo1 :
        (sel == 2) ? g_tfWi2 : (sel == 3) ? g_tfWo2 :
        (sel == 4) ? g_tfWi3 : (sel == 5) ? g_tfWo3 :
        (sel == 6) ? g_tfuWi : g_tfuWo;
    int i = blockIdx.x * blockDim.x + threadIdx.x;
    if (i < n) dst[i] = f2tf(src[i]);
}

// ---------------- CSR build ----------------
__global__ void zero_counts_kernel(int n) {
    int i = blockIdx.x * blockDim.x + threadIdx.x;
    if (i < n) g_counts[i] = 0;
}

__global__ void count_kernel(const int* __restrict__ atoms, int n) {
    for (int i = blockIdx.x * blockDim.x + threadIdx.x; i < n; i += gridDim.x * blockDim.x)
        atomicAdd(&g_counts[atoms[i]], 1);
}

__global__ void scan_kernel(int n) {
    __shared__ int wsum[32];
    __shared__ int sbase_sh;
    int tid = threadIdx.x, lane = tid & 31, wid = tid >> 5;
    if (tid == 0) sbase_sh = 0;
    __syncthreads();
    for (int base = 0; base < n; base += 1024) {
        int i = base + tid;
        int v = (i < n) ? g_counts[i] : 0;
        int x = v;
        #pragma unroll
        for (int o = 1; o < 32; o <<= 1) {
            int y = __shfl_up_sync(0xFFFFFFFFu, x, o);
            if (lane >= o) x += y;
        }
        if (lane == 31) wsum[wid] = x;
        __syncthreads();
        if (wid == 0) {
            int s = wsum[lane];
            #pragma unroll
            for (int o = 1; o < 32; o <<= 1) {
                int y = __shfl_up_sync(0xFFFFFFFFu, s, o);
                if (lane >= o) s += y;
            }
            wsum[lane] = s;
        }
        __syncthreads();
        int winc = (wid > 0) ? wsum[wid - 1] : 0;
        int incl = x + winc;
        int excl = sbase_sh + incl - v;
        if (i < n) { g_rowptr[i] = excl; g_cursor[i] = excl; }
        __syncthreads();
        if (tid == 1023) sbase_sh += incl;
        __syncthreads();
    }
    if (threadIdx.x == 0) g_rowptr[n] = sbase_sh;
}

__global__ void fill_kernel(const int* __restrict__ atoms, int n, int rowOff) {
    for (int i = blockIdx.x * blockDim.x + threadIdx.x; i < n; i += gridDim.x * blockDim.x) {
        int node = atoms[i];
        int pos = atomicAdd(&g_cursor[node], 1);
        g_colidx[pos] = rowOff + i;
    }
}

// ---------------- relation MLP (TF32 MMA, pipelined weight staging) ----------------
// y = x + mish(x@Wi+bi)@Wo+bo over gathered rows; messages -> g_msgs.
// R selects the pre-converted weight pair. Tiling identical to R3 (known-correct).
template <int S, int A, int R>
__global__ void __launch_bounds__(256)
rel_kernel(const float* __restrict__ hext, int hsel,
           const int* __restrict__ atoms, int m,
           const float* __restrict__ bi, const float* __restrict__ bo,
           long long outOff)
{
    constexpr int BM  = 64;
    constexpr int NT  = S / 32;
    constexpr int KC  = S / 16;
    constexpr int XST = S + 4;
    constexpr int WST = S + 8;
    constexpr int S4  = S / 4;
    constexpr int PF  = S / 64;            // uint4 loads per thread per chunk

    extern __shared__ unsigned sm[];
    unsigned* xs  = sm;                    // BM * XST
    unsigned* ts  = xs + BM * XST;         // BM * XST
    unsigned* ws0 = ts + BM * XST;         // 16 * WST
    unsigned* ws1 = ws0 + 16 * WST;        // 16 * WST
    int* sidx = (int*)(ws1 + 16 * WST);    // BM * A

    const unsigned* Wi = (R == 1) ? g_tfWi1 : (R == 2) ? g_tfWi2 : g_tfWi3;
    const unsigned* Wo = (R == 1) ? g_tfWo1 : (R == 2) ? g_tfWo2 : g_tfWo3;
    const uint4* Wi4 = (const uint4*)Wi;
    const uint4* Wo4 = (const uint4*)Wo;

    const float* h = (hsel == 0) ? hext : ((hsel == 1) ? g_hA : g_hB);
    float* out = g_msgs + outOff;

    const int tid  = threadIdx.x;
    const int lane = tid & 31;
    const int warp = tid >> 5;
    const int rg   = warp & 1;
    const int cg   = warp >> 1;
    const int gid  = lane >> 2;
    const int ctg  = lane & 3;
    const int row0 = blockIdx.x * BM;

    if (tid < BM * A) {
        int t = row0 * A + tid;
        sidx[tid] = (t < m * A) ? atoms[t] : 0;
    }
    __syncthreads();

    // gather x rows -> tf32 smem
    const float4* h4 = (const float4*)h;
    #pragma unroll
    for (int v = 0; v < S / 16; v++) {
        int u = tid + v * 256;
        int r = u / S4;
        int rem = u - r * S4;
        int node = sidx[r * A + (rem >> 4)];
        float4 val = h4[(size_t)node * 16 + (rem & 15)];
        ((uint4*)xs)[r * (S4 + 1) + rem] = make_uint4(f2tf(val.x), f2tf(val.y), f2tf(val.z), f2tf(val.w));
    }

    // prologue: stage Wi chunk 0 -> ws0
    {
        uint4 pre[PF];
        #pragma unroll
        for (int v = 0; v < PF; v++) pre[v] = Wi4[tid + v * 256];
        #pragma unroll
        for (int v = 0; v < PF; v++) {
            int u = tid + v * 256;
            int rr = u / S4, c4 = u - rr * S4;
            ((uint4*)ws0)[rr * (WST / 4) + c4] = pre[v];
        }
    }
    __syncthreads();

    float acc[2][NT][4];
    #pragma unroll
    for (int mt = 0; mt < 2; mt++)
        #pragma unroll
        for (int nt = 0; nt < NT; nt++)
            #pragma unroll
            for (int q = 0; q < 4; q++) acc[mt][nt][q] = 0.f;

    const int rb = rg * 32 + gid;
    const int cb = cg * (S / 4);

    // ---- GEMM1 (pipelined) ----
    unsigned* cur = ws0;
    unsigned* nxt = ws1;
    for (int kc = 0; kc < KC; kc++) {
        uint4 pre[PF];
        if (kc + 1 < KC) {
            #pragma unroll
            for (int v = 0; v < PF; v++) pre[v] = Wi4[(kc + 1) * 4 * S + tid + v * 256];
        }
        #pragma unroll
        for (int ks = 0; ks < 2; ks++) {
            int acol = kc * 16 + ks * 8 + ctg;
            unsigned a[2][4];
            #pragma unroll
            for (int mt = 0; mt < 2; mt++) {
                const unsigned* ap = xs + (rb + mt * 16) * XST + acol;
                a[mt][0] = ap[0];
                a[mt][1] = ap[8 * XST];
                a[mt][2] = ap[4];
                a[mt][3] = ap[8 * XST + 4];
            }
            #pragma unroll
            for (int nt = 0; nt < NT; nt++) {
                int bcol = cb + nt * 8 + gid;
                unsigned b0 = cur[(ks * 8 + ctg) * WST + bcol];
                unsigned b1 = cur[(ks * 8 + ctg + 4) * WST + bcol];
                mma8(acc[0][nt], a[0][0], a[0][1], a[0][2], a[0][3], b0, b1);
                mma8(acc[1][nt], a[1][0], a[1][1], a[1][2], a[1][3], b0, b1);
            }
        }
        if (kc + 1 < KC) {
            #pragma unroll
            for (int v = 0; v < PF; v++) {
                int u = tid + v * 256;
                int rr = u / S4, c4 = u - rr * S4;
                ((uint4*)nxt)[rr * (WST / 4) + c4] = pre[v];
            }
        }
        __syncthreads();
        unsigned* tmp = cur; cur = nxt; nxt = tmp;
    }

    // prefetch Wo chunk 0 while doing mish
    uint4 preW[PF];
    #pragma unroll
    for (int v = 0; v < PF; v++) preW[v] = Wo4[tid + v * 256];

    // bias + mish -> ts
    #pragma unroll
    for (int mt = 0; mt < 2; mt++) {
        int rA = rg * 32 + mt * 16 + gid;
        #pragma unroll
        for (int nt = 0; nt < NT; nt++) {
            int c0 = cb + nt * 8 + 2 * ctg;
            float b0v = __ldg(&bi[c0]), b1v = __ldg(&bi[c0 + 1]);
            ts[rA * XST + c0]           = f2tf(mishf(acc[mt][nt][0] + b0v));
            ts[rA * XST + c0 + 1]       = f2tf(mishf(acc[mt][nt][1] + b1v));
            ts[(rA + 8) * XST + c0]     = f2tf(mishf(acc[mt][nt][2] + b0v));
            ts[(rA + 8) * XST + c0 + 1] = f2tf(mishf(acc[mt][nt][3] + b1v));
        }
    }

    // GEMM2 init: acc = x + bo
    #pragma unroll
    for (int mt = 0; mt < 2; mt++) {
        int rA = rg * 32 + mt * 16 + gid;
        #pragma unroll
        for (int nt = 0; nt < NT; nt++) {
            int c0 = cb + nt * 8 + 2 * ctg;
            float b0v = __ldg(&bo[c0]), b1v = __ldg(&bo[c0 + 1]);
            acc[mt][nt][0] = __uint_as_float(xs[rA * XST + c0]) + b0v;
            acc[mt][nt][1] = __uint_as_float(xs[rA * XST + c0 + 1]) + b1v;
            acc[mt][nt][2] = __uint_as_float(xs[(rA + 8) * XST + c0]) + b0v;
            acc[mt][nt][3] = __uint_as_float(xs[(rA + 8) * XST + c0 + 1]) + b1v;
        }
    }

    // stage Wo chunk 0 -> ws0
    #pragma unroll
    for (int v = 0; v < PF; v++) {
        int u = tid + v * 256;
        int rr = u / S4, c4 = u - rr * S4;
        ((uint4*)ws0)[rr * (WST / 4) + c4] = preW[v];
    }
    __syncthreads();

    // ---- GEMM2 (pipelined) ----
    cur = ws0; nxt = ws1;
    for (int kc = 0; kc < KC; kc++) {
        uint4 pre[PF];
        if (kc + 1 < KC) {
            #pragma unroll
            for (int v = 0; v < PF; v++) pre[v] = Wo4[(kc + 1) * 4 * S + tid + v * 256];
        }
        #pragma unroll
        for (int ks = 0; ks < 2; ks++) {
            int acol = kc * 16 + ks * 8 + ctg;
            unsigned a[2][4];
            #pragma unroll
            for (int mt = 0; mt < 2; mt++) {
                const unsigned* ap = ts + (rb + mt * 16) * XST + acol;
                a[mt][0] = ap[0];
                a[mt][1] = ap[8 * XST];
                a[mt][2] = ap[4];
                a[mt][3] = ap[8 * XST + 4];
            }
            #pragma unroll
            for (int nt = 0; nt < NT; nt++) {
                int bcol = cb + nt * 8 + gid;
                unsigned b0 = cur[(ks * 8 + ctg) * WST + bcol];
                unsigned b1 = cur[(ks * 8 + ctg + 4) * WST + bcol];
                mma8(acc[0][nt], a[0][0], a[0][1], a[0][2], a[0][3], b0, b1);
                mma8(acc[1][nt], a[1][0], a[1][1], a[1][2], a[1][3], b0, b1);
            }
        }
        if (kc + 1 < KC) {
            #pragma unroll
            for (int v = 0; v < PF; v++) {
                int u = tid + v * 256;
                int rr = u / S4, c4 = u - rr * S4;
                ((uint4*)nxt)[rr * (WST / 4) + c4] = pre[v];
            }
        }
        __syncthreads();
        unsigned* tmp = cur; cur = nxt; nxt = tmp;
    }

    // ---- store messages (float2) ----
    #pragma unroll
    for (int mt = 0; mt < 2; mt++) {
        int rA = row0 + rg * 32 + mt * 16 + gid;
        #pragma unroll
        for (int nt = 0; nt < NT; nt++) {
            int c0 = cb + nt * 8 + 2 * ctg;
            if (rA < m)
                *(float2*)&out[(size_t)rA * S + c0] = make_float2(acc[mt][nt][0], acc[mt][nt][1]);
            if (rA + 8 < m)
                *(float2*)&out[(size_t)(rA + 8) * S + c0] = make_float2(acc[mt][nt][2], acc[mt][nt][3]);
        }
    }
}

// ---------------- smooth-max aggregation (one warp per node) ----------------
__global__ void agg_kernel(int n) {
    int w = (blockIdx.x * blockDim.x + threadIdx.x) >> 5;
    if (w >= n) return;
    int lane = threadIdx.x & 31;
    int s = g_rowptr[w], e = g_rowptr[w + 1];

    float m1 = -INFINITY, m2 = -INFINITY, s1 = 0.f, s2 = 0.f;
    int i = s;
    for (; i + 2 <= e; i += 2) {
        int r0 = __ldg(&g_colidx[i]);
        int r1 = __ldg(&g_colidx[i + 1]);
        const float* p0 = g_msgs + (size_t)r0 * 64;
        const float* p1 = g_msgs + (size_t)r1 * 64;
        float a0 = p0[lane], a1 = p0[lane + 32];
        float b0 = p1[lane], b1 = p1[lane + 32];
        smax_upd(m1, s1, a0); smax_upd(m2, s2, a1);
        smax_upd(m1, s1, b0); smax_upd(m2, s2, b1);
    }
    if (i < e) {
        int r0 = __ldg(&g_colidx[i]);
        const float* p0 = g_msgs + (size_t)r0 * 64;
        smax_upd(m1, s1, p0[lane]); smax_upd(m2, s2, p0[lane + 32]);
    }
    if (s == e) { m1 = 0.f; m2 = 0.f; }

    const float inv = 1.f / 12.f;
    g_maxmsg[(size_t)w * 64 + lane]      = __logf(1e-16f + s1) * inv + m1;
    g_maxmsg[(size_t)w * 64 + lane + 32] = __logf(1e-16f + s2) * inv + m2;
}

// ---------------- update MLP (TF32 MMA, pipelined) ----------------
__global__ void __launch_bounds__(256)
update_kernel(const float* __restrict__ hext, int hinsel, int houtsel, int n,
              const float* __restrict__ bi, const float* __restrict__ bo)
{
    constexpr int XST = 132;
    constexpr int WST = 136;
    extern __shared__ unsigned sm[];
    unsigned* xs  = sm;                  // 64*132
    unsigned* ts  = xs + 64 * XST;       // 64*132
    unsigned* ws0 = ts + 64 * XST;       // 16*136
    unsigned* ws1 = ws0 + 16 * WST;      // 16*136

    const float* hin = (hinsel == 0) ? hext : ((hinsel == 1) ? g_hA : g_hB);
    float* hout = (houtsel == 1) ? g_hA : g_hB;

    const uint4* Wi4 = (const uint4*)g_tfuWi;
    const uint4* Wo4 = (const uint4*)g_tfuWo;

    const int tid  = threadIdx.x;
    const int lane = tid & 31;
    const int warp = tid >> 5;
    const int rg   = warp & 1;
    const int cg   = warp >> 1;
    const int gid  = lane >> 2;
    const int ctg  = lane & 3;
    const int row0 = blockIdx.x * 64;

    // stage [maxmsg | h] -> xs (tf32)
    const float4* h4 = (const float4*)hin;
    const float4* mm4 = (const float4*)g_maxmsg;
    #pragma unroll
    for (int v = 0; v < 8; v++) {
        int u = tid + v * 256;
        int r = u >> 5, c4 = u & 31;
        float4 val = (c4 < 16) ? mm4[(size_t)(row0 + r) * 16 + c4]
                               : h4[(size_t)(row0 + r) * 16 + (c4 - 16)];
        ((uint4*)xs)[r * 33 + c4] = make_uint4(f2tf(val.x), f2tf(val.y), f2tf(val.z), f2tf(val.w));
    }
    // prologue: Wi chunk 0
    {
        uint4 pre0 = Wi4[tid], pre1 = Wi4[tid + 256];
        int u0 = tid, u1 = tid + 256;
        ((uint4*)ws0)[(u0 >> 5) * 34 + (u0 & 31)] = pre0;
        ((uint4*)ws0)[(u1 >> 5) * 34 + (u1 & 31)] = pre1;
    }
    __syncthreads();

    const int rb = rg * 32 + gid;

    // ---- GEMM1: [64,128]@[128,128] ----
    float acc[2][4][4];
    #pragma unroll
    for (int mt = 0; mt < 2; mt++)
        #pragma unroll
        for (int nt = 0; nt < 4; nt++)
            #pragma unroll
            for (int q = 0; q < 4; q++) acc[mt][nt][q] = 0.f;

    unsigned* cur = ws0;
    unsigned* nxt = ws1;
    for (int kc = 0; kc < 8; kc++) {
        uint4 pre0, pre1;
        if (kc + 1 < 8) {
            pre0 = Wi4[(kc + 1) * 512 + tid];
            pre1 = Wi4[(kc + 1) * 512 + tid + 256];
        }
        #pragma unroll
        for (int ks = 0; ks < 2; ks++) {
            int acol = kc * 16 + ks * 8 + ctg;
            unsigned a[2][4];
            #pragma unroll
            for (int mt = 0; mt < 2; mt++) {
                const unsigned* ap = xs + (rb + mt * 16) * XST + acol;
                a[mt][0] = ap[0];
                a[mt][1] = ap[8 * XST];
                a[mt][2] = ap[4];
                a[mt][3] = ap[8 * XST + 4];
            }
            #pragma unroll
            for (int nt = 0; nt < 4; nt++) {
                int bcol = cg * 32 + nt * 8 + gid;
                unsigned b0 = cur[(ks * 8 + ctg) * WST + bcol];
                unsigned b1 = cur[(ks * 8 + ctg + 4) * WST + bcol];
                mma8(acc[0][nt], a[0][0], a[0][1], a[0][2], a[0][3], b0, b1);
                mma8(acc[1][nt], a[1][0], a[1][1], a[1][2], a[1][3], b0, b1);
            }
        }
        if (kc + 1 < 8) {
            ((uint4*)nxt)[(tid >> 5) * 34 + (tid & 31)] = pre0;
            int u1 = tid + 256;
            ((uint4*)nxt)[(u1 >> 5) * 34 + (u1 & 31)] = pre1;
        }
        __syncthreads();
        unsigned* tmp = cur; cur = nxt; nxt = tmp;
    }

    // prefetch Wo chunk 0
    uint4 preW = Wo4[tid];

    // bias + mish -> ts
    #pragma unroll
    for (int mt = 0; mt < 2; mt++) {
        int rA = rg * 32 + mt * 16 + gid;
        #pragma unroll
        for (int nt = 0; nt < 4; nt++) {
            int c0 = cg * 32 + nt * 8 + 2 * ctg;
            float b0v = __ldg(&bi[c0]), b1v = __ldg(&bi[c0 + 1]);
            ts[rA * XST + c0]           = f2tf(mishf(acc[mt][nt][0] + b0v));
            ts[rA * XST + c0 + 1]       = f2tf(mishf(acc[mt][nt][1] + b1v));
            ts[(rA + 8) * XST + c0]     = f2tf(mishf(acc[mt][nt][2] + b0v));
            ts[(rA + 8) * XST + c0 + 1] = f2tf(mishf(acc[mt][nt][3] + b1v));
        }
    }

    // GEMM2 init: residual h + bo
    float acc2[2][2][4];
    #pragma unroll
    for (int mt = 0; mt < 2; mt++) {
        int rA = rg * 32 + mt * 16 + gid;
        #pragma unroll
        for (int nt = 0; nt < 2; nt++) {
            int c0 = cg * 16 + nt * 8 + 2 * ctg;
            float b0v = __ldg(&bo[c0]), b1v = __ldg(&bo[c0 + 1]);
            acc2[mt][nt][0] = __uint_as_float(xs[rA * XST + 64 + c0]) + b0v;
            acc2[mt][nt][1] = __uint_as_float(xs[rA * XST + 64 + c0 + 1]) + b1v;
            acc2[mt][nt][2] = __uint_as_float(xs[(rA + 8) * XST + 64 + c0]) + b0v;
            acc2[mt][nt][3] = __uint_as_float(xs[(rA + 8) * XST + 64 + c0 + 1]) + b1v;
        }
    }

    ((uint4*)ws0)[(tid >> 4) * 34 + (tid & 15)] = preW;
    __syncthreads();

    // ---- GEMM2: [64,128]@[128,64] ----
    cur = ws0; nxt = ws1;
    for (int kc = 0; kc < 8; kc++) {
        uint4 pre;
        if (kc + 1 < 8) pre = Wo4[(kc + 1) * 256 + tid];
        #pragma unroll
        for (int ks = 0; ks < 2; ks++) {
            int acol = kc * 16 + ks * 8 + ctg;
            unsigned a[2][4];
            #pragma unroll
            for (int mt = 0; mt < 2; mt++) {
                const unsigned* ap = ts + (rb + mt * 16) * XST + acol;
                a[mt][0] = ap[0];
                a[mt][1] = ap[8 * XST];
                a[mt][2] = ap[4];
                a[mt][3] = ap[8 * XST + 4];
            }
            #pragma unroll
            for (int nt = 0; nt < 2; nt++) {
                int bcol = cg * 16 + nt * 8 + gid;
                unsigned b0 = cur[(ks * 8 + ctg) * WST + bcol];
                unsigned b1 = cur[(ks * 8 + ctg + 4) * WST + bcol];
                mma8(acc2[0][nt], a[0][0], a[0][1], a[0][2], a[0][3], b0, b1);
                mma8(acc2[1][nt], a[1][0], a[1][1], a[1][2], a[1][3], b0, b1);
            }
        }
        if (kc + 1 < 8) ((uint4*)nxt)[(tid >> 4) * 34 + (tid & 15)] = pre;
        __syncthreads();
        unsigned* tmp = cur; cur = nxt; nxt = tmp;
    }

    #pragma unroll
    for (int mt = 0; mt < 2; mt++) {
        int rA = row0 + rg * 32 + mt * 16 + gid;
        #pragma unroll
        for (int nt = 0; nt < 2; nt++) {
            int c0 = cg * 16 + nt * 8 + 2 * ctg;
            if (rA < n)
                *(float2*)&hout[(size_t)rA * 64 + c0] = make_float2(acc2[mt][nt][0], acc2[mt][nt][1]);
            if (rA + 8 < n)
                *(float2*)&hout[(size_t)(rA + 8) * 64 + c0] = make_float2(acc2[mt][nt][2], acc2[mt][nt][3]);
        }
    }
}

// ---------------- readout ----------------
__global__ void bounds_kernel(const int* __restrict__ tok, int B) {
    if (threadIdx.x == 0) {
        int c = 0;
        g_bounds[0] = 0;
        for (int i = 0; i < B; i++) { c += tok[i]; g_bounds[i + 1] = c; }
    }
}

__global__ void segsum_kernel() {
    int b = blockIdx.x;
    int s = g_bounds[b], e = g_bounds[b + 1];
    int f = threadIdx.x & 63, g = threadIdx.x >> 6;
    float a = 0.f;
    for (int r = s + g; r < e; r += 4) a += g_hB[(size_t)r * 64 + f];
    __shared__ float red[256];
    red[threadIdx.x] = a;
    __syncthreads();
    if (g == 0) g_agg[b * 64 + f] = red[f] + red[64 + f] + red[128 + f] + red[192 + f];
}

__global__ void heads_kernel(const float* __restrict__ vWi, const float* __restrict__ vbi,
                             const float* __restrict__ vWo, const float* __restrict__ vbo,
                             const float* __restrict__ dWi, const float* __restrict__ dbi,
                             const float* __restrict__ dWo, const float* __restrict__ dbo,
                             float* __restrict__ out, int B)
{
    int b = blockIdx.x, o = threadIdx.x;
    __shared__ float a[64];
    __shared__ float red[64];
    a[o] = g_agg[b * 64 + o];
    __syncthreads();

    float t = vbi[o];
    for (int i = 0; i < 64; i++) t = fmaf(a[i], vWi[i * 64 + o], t);
    red[o] = mishf(t) * vWo[o];
    __syncthreads();
    for (int s = 32; s > 0; s >>= 1) {
        if (o < s) red[o] += red[o + s];
        __syncthreads();
    }
    if (o == 0) out[b] = red[0] + vbo[0];
    __syncthreads();

    t = dbi[o];
    for (int i = 0; i < 64; i++) t = fmaf(a[i], dWi[i * 64 + o], t);
    red[o] = mishf(t) * dWo[o];
    __syncthreads();
    for (int s = 32; s > 0; s >>= 1) {
        if (o < s) red[o] += red[o + s];
        __syncthreads();
    }
    if (o == 0) out[B + b] = red[0] + dbo[0];
}

// ---------------- host launch ----------------
static inline int smem_rel(int S, int A) {
    return (2 * 64 * (S + 4) + 32 * (S + 8)) * 4 + 64 * A * 4;
}

extern "C" void kernel_launch(void* const* d_in, const int* in_sizes, int n_in,
                              void* d_out, int out_size)
{
    if (n_in < 29) return;
    const float* h0  = (const float*)d_in[0];
    const int*   a1  = (const int*)d_in[1];  int n1 = in_sizes[1];
    const int*   a2  = (const int*)d_in[2];  int n2 = in_sizes[2];
    const int*   a3  = (const int*)d_in[3];  int n3 = in_sizes[3];
    const int*   tok = (const int*)d_in[4];  int B  = in_sizes[4];
    const float* Wi1 = (const float*)d_in[5],  *bi1 = (const float*)d_in[6];
    const float* Wo1 = (const float*)d_in[7],  *bo1 = (const float*)d_in[8];
    const float* Wi2 = (const float*)d_in[9],  *bi2 = (const float*)d_in[10];
    const float* Wo2 = (const float*)d_in[11], *bo2 = (const float*)d_in[12];
    const float* Wi3 = (const float*)d_in[13], *bi3 = (const float*)d_in[14];
    const float* Wo3 = (const float*)d_in[15], *bo3 = (const float*)d_in[16];
    const float* uWi = (const float*)d_in[17], *ubi = (const float*)d_in[18];
    const float* uWo = (const float*)d_in[19], *ubo = (const float*)d_in[20];
    const float* vWi = (const float*)d_in[21], *vbi = (const float*)d_in[22];
    const float* vWo = (const float*)d_in[23], *vbo = (const float*)d_in[24];
    const float* dWi = (const float*)d_in[25], *dbi = (const float*)d_in[26];
    const float* dWo = (const float*)d_in[27], *dbo = (const float*)d_in[28];
    float* out = (float*)d_out;

    int N = in_sizes[0] / 64;
    int m1 = n1, m2 = n2 / 2, m3 = n3 / 3;

    const int SM1 = smem_rel(64, 1);
    const int SM2 = smem_rel(128, 2);
    const int SM3 = smem_rel(192, 3);
    const int SMU = (2 * 64 * 132 + 32 * 136) * 4;

    cudaFuncSetAttribute(rel_kernel<64, 1, 1>,  cudaFuncAttributeMaxDynamicSharedMemorySize, SM1);
    cudaFuncSetAttribute(rel_kernel<128, 2, 2>, cudaFuncAttributeMaxDynamicSharedMemorySize, SM2);
    cudaFuncSetAttribute(rel_kernel<192, 3, 3>, cudaFuncAttributeMaxDynamicSharedMemorySize, SM3);
    cudaFuncSetAttribute(update_kernel,         cudaFuncAttributeMaxDynamicSharedMemorySize, SMU);

    // ---- weight pre-conversion ----
    conv_kernel<<<(64 * 64 + 255) / 256, 256>>>(Wi1, 0, 64 * 64);
    conv_kernel<<<(64 * 64 + 255) / 256, 256>>>(Wo1, 1, 64 * 64);
    conv_kernel<<<(128 * 128 + 255) / 256, 256>>>(Wi2, 2, 128 * 128);
    conv_kernel<<<(128 * 128 + 255) / 256, 256>>>(Wo2, 3, 128 * 128);
    conv_kernel<<<(192 * 192 + 255) / 256, 256>>>(Wi3, 4, 192 * 192);
    conv_kernel<<<(192 * 192 + 255) / 256, 256>>>(Wo3, 5, 192 * 192);
    conv_kernel<<<(128 * 128 + 255) / 256, 256>>>(uWi, 6, 128 * 128);
    conv_kernel<<<(128 * 64 + 255) / 256, 256>>>(uWo, 7, 128 * 64);

    // ---- CSR build ----
    zero_counts_kernel<<<(N + 255) / 256, 256>>>(N);
    count_kernel<<<512, 256>>>(a1, n1);
    count_kernel<<<512, 256>>>(a2, n2);
    count_kernel<<<512, 256>>>(a3, n3);
    scan_kernel<<<1, 1024>>>(N);
    fill_kernel<<<512, 256>>>(a1, n1, 0);
    fill_kernel<<<512, 256>>>(a2, n2, n1);
    fill_kernel<<<512, 256>>>(a3, n3, n1 + n2);

    // ---- two GNN layers ----
    for (int layer = 0; layer < 2; layer++) {
        int hsel = (layer == 0) ? 0 : 1;
        rel_kernel<64, 1, 1><<<(m1 + 63) / 64, 256, SM1>>>(h0, hsel, a1, m1, bi1, bo1, 0LL);
        rel_kernel<128, 2, 2><<<(m2 + 63) / 64, 256, SM2>>>(h0, hsel, a2, m2, bi2, bo2, (long long)n1 * 64);
        rel_kernel<192, 3, 3><<<(m3 + 63) / 64, 256, SM3>>>(h0, hsel, a3, m3, bi3, bo3, (long long)(n1 + n2) * 64);
        agg_kernel<<<(N + 7) / 8, 256>>>(N);
        update_kernel<<<(N + 63) / 64, 256, SMU>>>(h0, hsel, (layer == 0) ? 1 : 2, N, ubi, ubo);
    }

    // ---- readout ----
    bounds_kernel<<<1, 32>>>(tok, B);
    segsum_kernel<<<B, 256>>>();
    heads_kernel<<<B, 64>>>(vWi, vbi, vWo, vbo, dWi, dbi, dWo, dbo, out, B);
}

// round 5
// speedup vs baseline: 1.2743x; 1.2743x over previous
#include <cuda_runtime.h>
#include <math.h>
#include <stdint.h>

// ---------------- static scratch (no allocations allowed) ----------------
#define NMAX   131072
#define TMAX   1700000

__device__ float g_msgs[(size_t)TMAX * 64];
__device__ int   g_colidx[TMAX];
__device__ int   g_counts[NMAX];
__device__ int   g_rowptr[NMAX + 1];
__device__ int   g_cursor[NMAX];
__device__ float g_hA[(size_t)NMAX * 64];
__device__ float g_hB[(size_t)NMAX * 64];
__device__ float g_maxmsg[(size_t)NMAX * 64];
__device__ int   g_bounds[257];
__device__ float g_agg[256 * 64];

// pre-converted tf32 weights
__device__ unsigned g_tfWi1[64 * 64],   g_tfWo1[64 * 64];
__device__ unsigned g_tfWi2[128 * 128], g_tfWo2[128 * 128];
__device__ unsigned g_tfWi3[192 * 192], g_tfWo3[192 * 192];
__device__ unsigned g_tfuWi[128 * 128], g_tfuWo[128 * 64];

// ---------------- math helpers ----------------
__device__ __forceinline__ float mishf(float x) {
    if (x > 20.f) return x;
    float e = __expf(x);
    float n = e * (e + 2.f);
    return x * (n / (n + 2.f));
}

__device__ __forceinline__ void smax_upd(float& m, float& s, float v) {
    if (v > m) { s = s * __expf(12.f * (m - v)) + 1.f; m = v; }
    else       { s += __expf(12.f * (v - m)); }
}

__device__ __forceinline__ unsigned f2tf(float x) {
    unsigned r;
    asm("cvt.rna.tf32.f32 %0, %1;" : "=r"(r) : "f"(x));
    return r;
}

__device__ __forceinline__ void mma8(float* c, unsigned a0, unsigned a1, unsigned a2, unsigned a3,
                                     unsigned b0, unsigned b1) {
    asm volatile(
        "mma.sync.aligned.m16n8k8.row.col.f32.tf32.tf32.f32 "
        "{%0,%1,%2,%3}, {%4,%5,%6,%7}, {%8,%9}, {%0,%1,%2,%3};\n"
        : "+f"(c[0]), "+f"(c[1]), "+f"(c[2]), "+f"(c[3])
        : "r"(a0), "r"(a1), "r"(a2), "r"(a3), "r"(b0), "r"(b1));
}

// ---------------- fused weight pre-conversion (1 launch) ----------------
__global__ void conv_all_kernel(const float* __restrict__ Wi1, const float* __restrict__ Wo1,
                                const float* __restrict__ Wi2, const float* __restrict__ Wo2,
                                const float* __restrict__ Wi3, const float* __restrict__ Wo3,
                                const float* __restrict__ uWi, const float* __restrict__ uWo)
{
    int i = blockIdx.x * blockDim.x + threadIdx.x;
    // cumulative: 4096,8192,24576,40960,77824,114688,131072,139264
    if (i < 4096)            g_tfWi1[i] = f2tf(Wi1[i]);
    else if (i < 8192)       g_tfWo1[i - 4096] = f2tf(Wo1[i - 4096]);
    else if (i < 24576)      g_tfWi2[i - 8192] = f2tf(Wi2[i - 8192]);
    else if (i < 40960)      g_tfWo2[i - 24576] = f2tf(Wo2[i - 24576]);
    else if (i < 77824)      g_tfWi3[i - 40960] = f2tf(Wi3[i - 40960]);
    else if (i < 114688)     g_tfWo3[i - 77824] = f2tf(Wo3[i - 77824]);
    else if (i < 131072)     g_tfuWi[i - 114688] = f2tf(uWi[i - 114688]);
    else if (i < 139264)     g_tfuWo[i - 131072] = f2tf(uWo[i - 131072]);
}

// ---------------- CSR build ----------------
__global__ void zero_counts_kernel(int n) {
    int i = blockIdx.x * blockDim.x + threadIdx.x;
    if (i < n) g_counts[i] = 0;
}

__global__ void count_all_kernel(const int* __restrict__ a1, int n1,
                                 const int* __restrict__ a2, int n2,
                                 const int* __restrict__ a3, int n3)
{
    int total = n1 + n2 + n3;
    for (int i = blockIdx.x * blockDim.x + threadIdx.x; i < total; i += gridDim.x * blockDim.x) {
        int v = (i < n1) ? a1[i] : (i < n1 + n2) ? a2[i - n1] : a3[i - n1 - n2];
        atomicAdd(&g_counts[v], 1);
    }
}

__global__ void scan_kernel(int n) {
    __shared__ int wsum[32];
    __shared__ int sbase_sh;
    int tid = threadIdx.x, lane = tid & 31, wid = tid >> 5;
    if (tid == 0) sbase_sh = 0;
    __syncthreads();
    for (int base = 0; base < n; base += 1024) {
        int i = base + tid;
        int v = (i < n) ? g_counts[i] : 0;
        int x = v;
        #pragma unroll
        for (int o = 1; o < 32; o <<= 1) {
            int y = __shfl_up_sync(0xFFFFFFFFu, x, o);
            if (lane >= o) x += y;
        }
        if (lane == 31) wsum[wid] = x;
        __syncthreads();
        if (wid == 0) {
            int s = wsum[lane];
            #pragma unroll
            for (int o = 1; o < 32; o <<= 1) {
                int y = __shfl_up_sync(0xFFFFFFFFu, s, o);
                if (lane >= o) s += y;
            }
            wsum[lane] = s;
        }
        __syncthreads();
        int winc = (wid > 0) ? wsum[wid - 1] : 0;
        int incl = x + winc;
        int excl = sbase_sh + incl - v;
        if (i < n) { g_rowptr[i] = excl; g_cursor[i] = excl; }
        __syncthreads();
        if (tid == 1023) sbase_sh += incl;
        __syncthreads();
    }
    if (threadIdx.x == 0) g_rowptr[n] = sbase_sh;
}

__global__ void fill_all_kernel(const int* __restrict__ a1, int n1,
                                const int* __restrict__ a2, int n2,
                                const int* __restrict__ a3, int n3)
{
    int total = n1 + n2 + n3;
    for (int i = blockIdx.x * blockDim.x + threadIdx.x; i < total; i += gridDim.x * blockDim.x) {
        int v = (i < n1) ? a1[i] : (i < n1 + n2) ? a2[i - n1] : a3[i - n1 - n2];
        int pos = atomicAdd(&g_cursor[v], 1);
        g_colidx[pos] = i;   // global message-term index == layout order in g_msgs
    }
}

// ---------------- relation MLP (TF32 MMA, single aliased buffer) ----------------
// y = x + mish(x@Wi+bi)@Wo+bo over gathered rows; messages -> g_msgs.
template <int S, int A, int R>
__global__ void __launch_bounds__(256)
rel_kernel(const float* __restrict__ hext, int hsel,
           const int* __restrict__ atoms, int m,
           const float* __restrict__ bi, const float* __restrict__ bo,
           long long outOff)
{
    constexpr int BM  = 64;
    constexpr int NT  = S / 32;
    constexpr int KC  = S / 16;
    constexpr int XST = S + 4;
    constexpr int WST = S + 8;
    constexpr int S4  = S / 4;
    constexpr int PF  = S / 64;

    extern __shared__ unsigned sm[];
    unsigned* xs = sm;                     // BM * XST  (x, later mish(t))
    unsigned* ws = xs + BM * XST;          // 16 * WST
    int* sidx = (int*)(ws + 16 * WST);     // BM * A

    const unsigned* Wi = (R == 1) ? g_tfWi1 : (R == 2) ? g_tfWi2 : g_tfWi3;
    const unsigned* Wo = (R == 1) ? g_tfWo1 : (R == 2) ? g_tfWo2 : g_tfWo3;
    const uint4* Wi4 = (const uint4*)Wi;
    const uint4* Wo4 = (const uint4*)Wo;

    const float* h = (hsel == 0) ? hext : ((hsel == 1) ? g_hA : g_hB);
    float* out = g_msgs + outOff;

    const int tid  = threadIdx.x;
    const int lane = tid & 31;
    const int warp = tid >> 5;
    const int rg   = warp & 1;
    const int cg   = warp >> 1;
    const int gid  = lane >> 2;
    const int ctg  = lane & 3;
    const int row0 = blockIdx.x * BM;

    if (tid < BM * A) {
        int t = row0 * A + tid;
        sidx[tid] = (t < m * A) ? atoms[t] : 0;
    }
    __syncthreads();

    // gather x rows -> tf32 smem
    const float4* h4 = (const float4*)h;
    #pragma unroll
    for (int v = 0; v < S / 16; v++) {
        int u = tid + v * 256;
        int r = u / S4;
        int rem = u - r * S4;
        int node = sidx[r * A + (rem >> 4)];
        float4 val = h4[(size_t)node * 16 + (rem & 15)];
        ((uint4*)xs)[r * (S4 + 1) + rem] = make_uint4(f2tf(val.x), f2tf(val.y), f2tf(val.z), f2tf(val.w));
    }

    // prologue: stage Wi chunk 0
    {
        uint4 pre[PF];
        #pragma unroll
        for (int v = 0; v < PF; v++) pre[v] = Wi4[tid + v * 256];
        #pragma unroll
        for (int v = 0; v < PF; v++) {
            int u = tid + v * 256;
            int rr = u / S4, c4 = u - rr * S4;
            ((uint4*)ws)[rr * (WST / 4) + c4] = pre[v];
        }
    }
    __syncthreads();

    float acc[2][NT][4];
    #pragma unroll
    for (int mt = 0; mt < 2; mt++)
        #pragma unroll
        for (int nt = 0; nt < NT; nt++)
            #pragma unroll
            for (int q = 0; q < 4; q++) acc[mt][nt][q] = 0.f;

    const int rb = rg * 32 + gid;
    const int cb = cg * (S / 4);

    // ---- GEMM1: acc = x @ Wi ----
    for (int kc = 0; kc < KC; kc++) {
        uint4 pre[PF];
        if (kc + 1 < KC) {
            #pragma unroll
            for (int v = 0; v < PF; v++) pre[v] = Wi4[(kc + 1) * 4 * S + tid + v * 256];
        }
        #pragma unroll
        for (int ks = 0; ks < 2; ks++) {
            int acol = kc * 16 + ks * 8 + ctg;
            unsigned a[2][4];
            #pragma unroll
            for (int mt = 0; mt < 2; mt++) {
                const unsigned* ap = xs + (rb + mt * 16) * XST + acol;
                a[mt][0] = ap[0];
                a[mt][1] = ap[8 * XST];
                a[mt][2] = ap[4];
                a[mt][3] = ap[8 * XST + 4];
            }
            #pragma unroll
            for (int nt = 0; nt < NT; nt++) {
                int bcol = cb + nt * 8 + gid;
                unsigned b0 = ws[(ks * 8 + ctg) * WST + bcol];
                unsigned b1 = ws[(ks * 8 + ctg + 4) * WST + bcol];
                mma8(acc[0][nt], a[0][0], a[0][1], a[0][2], a[0][3], b0, b1);
                mma8(acc[1][nt], a[1][0], a[1][1], a[1][2], a[1][3], b0, b1);
            }
        }
        __syncthreads();
        if (kc + 1 < KC) {
            #pragma unroll
            for (int v = 0; v < PF; v++) {
                int u = tid + v * 256;
                int rr = u / S4, c4 = u - rr * S4;
                ((uint4*)ws)[rr * (WST / 4) + c4] = pre[v];
            }
            __syncthreads();
        }
    }

    // ---- bias + mish overwrite xs in place; acc := x + bo (residual) ----
    // Per thread: read xs[pos], write xs[pos] — same positions, no cross-thread hazard.
    #pragma unroll
    for (int mt = 0; mt < 2; mt++) {
        int rA = rg * 32 + mt * 16 + gid;
        #pragma unroll
        for (int nt = 0; nt < NT; nt++) {
            int c0 = cb + nt * 8 + 2 * ctg;
            float bi0 = __ldg(&bi[c0]), bi1 = __ldg(&bi[c0 + 1]);
            float bo0 = __ldg(&bo[c0]), bo1 = __ldg(&bo[c0 + 1]);
            unsigned* p0 = &xs[rA * XST + c0];
            unsigned* p1 = &xs[(rA + 8) * XST + c0];
            float x00 = __uint_as_float(p0[0]), x01 = __uint_as_float(p0[1]);
            float x10 = __uint_as_float(p1[0]), x11 = __uint_as_float(p1[1]);
            p0[0] = f2tf(mishf(acc[mt][nt][0] + bi0));
            p0[1] = f2tf(mishf(acc[mt][nt][1] + bi1));
            p1[0] = f2tf(mishf(acc[mt][nt][2] + bi0));
            p1[1] = f2tf(mishf(acc[mt][nt][3] + bi1));
            acc[mt][nt][0] = x00 + bo0;
            acc[mt][nt][1] = x01 + bo1;
            acc[mt][nt][2] = x10 + bo0;
            acc[mt][nt][3] = x11 + bo1;
        }
    }

    // stage Wo chunk 0
    {
        uint4 pre[PF];
        #pragma unroll
        for (int v = 0; v < PF; v++) pre[v] = Wo4[tid + v * 256];
        __syncthreads();   // mish writes visible + ws free
        #pragma unroll
        for (int v = 0; v < PF; v++) {
            int u = tid + v * 256;
            int rr = u / S4, c4 = u - rr * S4;
            ((uint4*)ws)[rr * (WST / 4) + c4] = pre[v];
        }
    }
    __syncthreads();

    // ---- GEMM2: acc += mish(.) @ Wo ----
    for (int kc = 0; kc < KC; kc++) {
        uint4 pre[PF];
        if (kc + 1 < KC) {
            #pragma unroll
            for (int v = 0; v < PF; v++) pre[v] = Wo4[(kc + 1) * 4 * S + tid + v * 256];
        }
        #pragma unroll
        for (int ks = 0; ks < 2; ks++) {
            int acol = kc * 16 + ks * 8 + ctg;
            unsigned a[2][4];
            #pragma unroll
            for (int mt = 0; mt < 2; mt++) {
                const unsigned* ap = xs + (rb + mt * 16) * XST + acol;
                a[mt][0] = ap[0];
                a[mt][1] = ap[8 * XST];
                a[mt][2] = ap[4];
                a[mt][3] = ap[8 * XST + 4];
            }
            #pragma unroll
            for (int nt = 0; nt < NT; nt++) {
                int bcol = cb + nt * 8 + gid;
                unsigned b0 = ws[(ks * 8 + ctg) * WST + bcol];
                unsigned b1 = ws[(ks * 8 + ctg + 4) * WST + bcol];
                mma8(acc[0][nt], a[0][0], a[0][1], a[0][2], a[0][3], b0, b1);
                mma8(acc[1][nt], a[1][0], a[1][1], a[1][2], a[1][3], b0, b1);
            }
        }
        __syncthreads();
        if (kc + 1 < KC) {
            #pragma unroll
            for (int v = 0; v < PF; v++) {
                int u = tid + v * 256;
                int rr = u / S4, c4 = u - rr * S4;
                ((uint4*)ws)[rr * (WST / 4) + c4] = pre[v];
            }
            __syncthreads();
        }
    }

    // ---- store messages (float2) ----
    #pragma unroll
    for (int mt = 0; mt < 2; mt++) {
        int rA = row0 + rg * 32 + mt * 16 + gid;
        #pragma unroll
        for (int nt = 0; nt < NT; nt++) {
            int c0 = cb + nt * 8 + 2 * ctg;
            if (rA < m)
                *(float2*)&out[(size_t)rA * S + c0] = make_float2(acc[mt][nt][0], acc[mt][nt][1]);
            if (rA + 8 < m)
                *(float2*)&out[(size_t)(rA + 8) * S + c0] = make_float2(acc[mt][nt][2], acc[mt][nt][3]);
        }
    }
}

// ---------------- smooth-max aggregation (one warp per node) ----------------
__global__ void agg_kernel(int n) {
    int w = (blockIdx.x * blockDim.x + threadIdx.x) >> 5;
    if (w >= n) return;
    int lane = threadIdx.x & 31;
    int s = g_rowptr[w], e = g_rowptr[w + 1];

    float m1 = -INFINITY, m2 = -INFINITY, s1 = 0.f, s2 = 0.f;
    int i = s;
    for (; i + 2 <= e; i += 2) {
        int r0 = __ldg(&g_colidx[i]);
        int r1 = __ldg(&g_colidx[i + 1]);
        const float* p0 = g_msgs + (size_t)r0 * 64;
        const float* p1 = g_msgs + (size_t)r1 * 64;
        float a0 = p0[lane], a1 = p0[lane + 32];
        float b0 = p1[lane], b1 = p1[lane + 32];
        smax_upd(m1, s1, a0); smax_upd(m2, s2, a1);
        smax_upd(m1, s1, b0); smax_upd(m2, s2, b1);
    }
    if (i < e) {
        int r0 = __ldg(&g_colidx[i]);
        const float* p0 = g_msgs + (size_t)r0 * 64;
        smax_upd(m1, s1, p0[lane]); smax_upd(m2, s2, p0[lane + 32]);
    }
    if (s == e) { m1 = 0.f; m2 = 0.f; }

    const float inv = 1.f / 12.f;
    g_maxmsg[(size_t)w * 64 + lane]      = __logf(1e-16f + s1) * inv + m1;
    g_maxmsg[(size_t)w * 64 + lane + 32] = __logf(1e-16f + s2) * inv + m2;
}

// ---------------- update MLP (TF32 MMA, aliased buffer) ----------------
__global__ void __launch_bounds__(256)
update_kernel(const float* __restrict__ hext, int hinsel, int houtsel, int n,
              const float* __restrict__ bi, const float* __restrict__ bo)
{
    constexpr int XST = 132;
    constexpr int WST = 136;
    extern __shared__ unsigned sm[];
    unsigned* xs = sm;                  // 64*132 ([maxmsg|h], later mish)
    unsigned* ws = xs + 64 * XST;       // 16*136

    const float* hin = (hinsel == 0) ? hext : ((hinsel == 1) ? g_hA : g_hB);
    float* hout = (houtsel == 1) ? g_hA : g_hB;

    const uint4* Wi4 = (const uint4*)g_tfuWi;
    const uint4* Wo4 = (const uint4*)g_tfuWo;

    const int tid  = threadIdx.x;
    const int lane = tid & 31;
    const int warp = tid >> 5;
    const int rg   = warp & 1;
    const int cg   = warp >> 1;
    const int gid  = lane >> 2;
    const int ctg  = lane & 3;
    const int row0 = blockIdx.x * 64;

    // stage [maxmsg | h] -> xs (tf32)
    const float4* h4 = (const float4*)hin;
    const float4* mm4 = (const float4*)g_maxmsg;
    #pragma unroll
    for (int v = 0; v < 8; v++) {
        int u = tid + v * 256;
        int r = u >> 5, c4 = u & 31;
        float4 val = (c4 < 16) ? mm4[(size_t)(row0 + r) * 16 + c4]
                               : h4[(size_t)(row0 + r) * 16 + (c4 - 16)];
        ((uint4*)xs)[r * 33 + c4] = make_uint4(f2tf(val.x), f2tf(val.y), f2tf(val.z), f2tf(val.w));
    }
    // prologue: Wi chunk 0
    {
        uint4 pre0 = Wi4[tid], pre1 = Wi4[tid + 256];
        ((uint4*)ws)[(tid >> 5) * 34 + (tid & 31)] = pre0;
        int u1 = tid + 256;
        ((uint4*)ws)[(u1 >> 5) * 34 + (u1 & 31)] = pre1;
    }
    __syncthreads();

    const int rb = rg * 32 + gid;

    // ---- GEMM1: [64,128]@[128,128] ----
    float acc[2][4][4];
    #pragma unroll
    for (int mt = 0; mt < 2; mt++)
        #pragma unroll
        for (int nt = 0; nt < 4; nt++)
            #pragma unroll
            for (int q = 0; q < 4; q++) acc[mt][nt][q] = 0.f;

    for (int kc = 0; kc < 8; kc++) {
        uint4 pre0, pre1;
        if (kc + 1 < 8) {
            pre0 = Wi4[(kc + 1) * 512 + tid];
            pre1 = Wi4[(kc + 1) * 512 + tid + 256];
        }
        #pragma unroll
        for (int ks = 0; ks < 2; ks++) {
            int acol = kc * 16 + ks * 8 + ctg;
            unsigned a[2][4];
            #pragma unroll
            for (int mt = 0; mt < 2; mt++) {
                const unsigned* ap = xs + (rb + mt * 16) * XST + acol;
                a[mt][0] = ap[0];
                a[mt][1] = ap[8 * XST];
                a[mt][2] = ap[4];
                a[mt][3] = ap[8 * XST + 4];
            }
            #pragma unroll
            for (int nt = 0; nt < 4; nt++) {
                int bcol = cg * 32 + nt * 8 + gid;
                unsigned b0 = ws[(ks * 8 + ctg) * WST + bcol];
                unsigned b1 = ws[(ks * 8 + ctg + 4) * WST + bcol];
                mma8(acc[0][nt], a[0][0], a[0][1], a[0][2], a[0][3], b0, b1);
                mma8(acc[1][nt], a[1][0], a[1][1], a[1][2], a[1][3], b0, b1);
            }
        }
        __syncthreads();
        if (kc + 1 < 8) {
            ((uint4*)ws)[(tid >> 5) * 34 + (tid & 31)] = pre0;
            int u1 = tid + 256;
            ((uint4*)ws)[(u1 >> 5) * 34 + (u1 & 31)] = pre1;
            __syncthreads();
        }
    }

    // ---- residual reads (cross-thread vs mish writes → sync between) ----
    float acc2[2][2][4];
    #pragma unroll
    for (int mt = 0; mt < 2; mt++) {
        int rA = rg * 32 + mt * 16 + gid;
        #pragma unroll
        for (int nt = 0; nt < 2; nt++) {
            int c0 = cg * 16 + nt * 8 + 2 * ctg;
            float bo0 = __ldg(&bo[c0]), bo1 = __ldg(&bo[c0 + 1]);
            acc2[mt][nt][0] = __uint_as_float(xs[rA * XST + 64 + c0]) + bo0;
            acc2[mt][nt][1] = __uint_as_float(xs[rA * XST + 64 + c0 + 1]) + bo1;
            acc2[mt][nt][2] = __uint_as_float(xs[(rA + 8) * XST + 64 + c0]) + bo0;
            acc2[mt][nt][3] = __uint_as_float(xs[(rA + 8) * XST + 64 + c0 + 1]) + bo1;
        }
    }
    __syncthreads();

    // mish overwrites xs (full 128 cols)
    #pragma unroll
    for (int mt = 0; mt < 2; mt++) {
        int rA = rg * 32 + mt * 16 + gid;
        #pragma unroll
        for (int nt = 0; nt < 4; nt++) {
            int c0 = cg * 32 + nt * 8 + 2 * ctg;
            float bi0 = __ldg(&bi[c0]), bi1 = __ldg(&bi[c0 + 1]);
            xs[rA * XST + c0]           = f2tf(mishf(acc[mt][nt][0] + bi0));
            xs[rA * XST + c0 + 1]       = f2tf(mishf(acc[mt][nt][1] + bi1));
            xs[(rA + 8) * XST + c0]     = f2tf(mishf(acc[mt][nt][2] + bi0));
            xs[(rA + 8) * XST + c0 + 1] = f2tf(mishf(acc[mt][nt][3] + bi1));
        }
    }

    // stage Wo chunk 0
    {
        uint4 preW = Wo4[tid];
        __syncthreads();
        ((uint4*)ws)[(tid >> 4) * 34 + (tid & 15)] = preW;
    }
    __syncthreads();

    // ---- GEMM2: [64,128]@[128,64] ----
    for (int kc = 0; kc < 8; kc++) {
        uint4 pre;
        if (kc + 1 < 8) pre = Wo4[(kc + 1) * 256 + tid];
        #pragma unroll
        for (int ks = 0; ks < 2; ks++) {
            int acol = kc * 16 + ks * 8 + ctg;
            unsigned a[2][4];
            #pragma unroll
            for (int mt = 0; mt < 2; mt++) {
                const unsigned* ap = xs + (rb + mt * 16) * XST + acol;
                a[mt][0] = ap[0];
                a[mt][1] = ap[8 * XST];
                a[mt][2] = ap[4];
                a[mt][3] = ap[8 * XST + 4];
            }
            #pragma unroll
            for (int nt = 0; nt < 2; nt++) {
                int bcol = cg * 16 + nt * 8 + gid;
                unsigned b0 = ws[(ks * 8 + ctg) * WST + bcol];
                unsigned b1 = ws[(ks * 8 + ctg + 4) * WST + bcol];
                mma8(acc2[0][nt], a[0][0], a[0][1], a[0][2], a[0][3], b0, b1);
                mma8(acc2[1][nt], a[1][0], a[1][1], a[1][2], a[1][3], b0, b1);
            }
        }
        __syncthreads();
        if (kc + 1 < 8) {
            ((uint4*)ws)[(tid >> 4) * 34 + (tid & 15)] = pre;
            __syncthreads();
        }
    }

    #pragma unroll
    for (int mt = 0; mt < 2; mt++) {
        int rA = row0 + rg * 32 + mt * 16 + gid;
        #pragma unroll
        for (int nt = 0; nt < 2; nt++) {
            int c0 = cg * 16 + nt * 8 + 2 * ctg;
            if (rA < n)
                *(float2*)&hout[(size_t)rA * 64 + c0] = make_float2(acc2[mt][nt][0], acc2[mt][nt][1]);
            if (rA + 8 < n)
                *(float2*)&hout[(size_t)(rA + 8) * 64 + c0] = make_float2(acc2[mt][nt][2], acc2[mt][nt][3]);
        }
    }
}

// ---------------- readout ----------------
__global__ void bounds_kernel(const int* __restrict__ tok, int B) {
    if (threadIdx.x == 0) {
        int c = 0;
        g_bounds[0] = 0;
        for (int i = 0; i < B; i++) { c += tok[i]; g_bounds[i + 1] = c; }
    }
}

__global__ void segsum_kernel() {
    int b = blockIdx.x;
    int s = g_bounds[b], e = g_bounds[b + 1];
    int f = threadIdx.x & 63, g = threadIdx.x >> 6;
    float a = 0.f;
    for (int r = s + g; r < e; r += 4) a += g_hB[(size_t)r * 64 + f];
    __shared__ float red[256];
    red[threadIdx.x] = a;
    __syncthreads();
    if (g == 0) g_agg[b * 64 + f] = red[f] + red[64 + f] + red[128 + f] + red[192 + f];
}

__global__ void heads_kernel(const float* __restrict__ vWi, const float* __restrict__ vbi,
                             const float* __restrict__ vWo, const float* __restrict__ vbo,
                             const float* __restrict__ dWi, const float* __restrict__ dbi,
                             const float* __restrict__ dWo, const float* __restrict__ dbo,
                             float* __restrict__ out, int B)
{
    int b = blockIdx.x, o = threadIdx.x;
    __shared__ float a[64];
    __shared__ float red[64];
    a[o] = g_agg[b * 64 + o];
    __syncthreads();

    float t = vbi[o];
    for (int i = 0; i < 64; i++) t = fmaf(a[i], vWi[i * 64 + o], t);
    red[o] = mishf(t) * vWo[o];
    __syncthreads();
    for (int s = 32; s > 0; s >>= 1) {
        if (o < s) red[o] += red[o + s];
        __syncthreads();
    }
    if (o == 0) out[b] = red[0] + vbo[0];
    __syncthreads();

    t = dbi[o];
    for (int i = 0; i < 64; i++) t = fmaf(a[i], dWi[i * 64 + o], t);
    red[o] = mishf(t) * dWo[o];
    __syncthreads();
    for (int s = 32; s > 0; s >>= 1) {
        if (o < s) red[o] += red[o + s];
        __syncthreads();
    }
    if (o == 0) out[B + b] = red[0] + dbo[0];
}

// ---------------- host launch ----------------
static inline int smem_rel(int S, int A) {
    return (64 * (S + 4) + 16 * (S + 8)) * 4 + 64 * A * 4;
}

extern "C" void kernel_launch(void* const* d_in, const int* in_sizes, int n_in,
                              void* d_out, int out_size)
{
    if (n_in < 29) return;
    const float* h0  = (const float*)d_in[0];
    const int*   a1  = (const int*)d_in[1];  int n1 = in_sizes[1];
    const int*   a2  = (const int*)d_in[2];  int n2 = in_sizes[2];
    const int*   a3  = (const int*)d_in[3];  int n3 = in_sizes[3];
    const int*   tok = (const int*)d_in[4];  int B  = in_sizes[4];
    const float* Wi1 = (const float*)d_in[5],  *bi1 = (const float*)d_in[6];
    const float* Wo1 = (const float*)d_in[7],  *bo1 = (const float*)d_in[8];
    const float* Wi2 = (const float*)d_in[9],  *bi2 = (const float*)d_in[10];
    const float* Wo2 = (const float*)d_in[11], *bo2 = (const float*)d_in[12];
    const float* Wi3 = (const float*)d_in[13], *bi3 = (const float*)d_in[14];
    const float* Wo3 = (const float*)d_in[15], *bo3 = (const float*)d_in[16];
    const float* uWi = (const float*)d_in[17], *ubi = (const float*)d_in[18];
    const float* uWo = (const float*)d_in[19], *ubo = (const float*)d_in[20];
    const float* vWi = (const float*)d_in[21], *vbi = (const float*)d_in[22];
    const float* vWo = (const float*)d_in[23], *vbo = (const float*)d_in[24];
    const float* dWi = (const float*)d_in[25], *dbi = (const float*)d_in[26];
    const float* dWo = (const float*)d_in[27], *dbo = (const float*)d_in[28];
    float* out = (float*)d_out;

    int N = in_sizes[0] / 64;
    int m1 = n1, m2 = n2 / 2, m3 = n3 / 3;

    const int SM1 = smem_rel(64, 1);
    const int SM2 = smem_rel(128, 2);
    const int SM3 = smem_rel(192, 3);
    const int SMU = (64 * 132 + 16 * 136) * 4;

    cudaFuncSetAttribute(rel_kernel<64, 1, 1>,  cudaFuncAttributeMaxDynamicSharedMemorySize, SM1);
    cudaFuncSetAttribute(rel_kernel<128, 2, 2>, cudaFuncAttributeMaxDynamicSharedMemorySize, SM2);
    cudaFuncSetAttribute(rel_kernel<192, 3, 3>, cudaFuncAttributeMaxDynamicSharedMemorySize, SM3);
    cudaFuncSetAttribute(update_kernel,         cudaFuncAttributeMaxDynamicSharedMemorySize, SMU);

    // launches 1-5, so ncu (-s 5 -c 1) captures launch #6 = rel_kernel<192>
    conv_all_kernel<<<(139264 + 255) / 256, 256>>>(Wi1, Wo1, Wi2, Wo2, Wi3, Wo3, uWi, uWo);
    zero_counts_kernel<<<(N + 255) / 256, 256>>>(N);
    count_all_kernel<<<1024, 256>>>(a1, n1, a2, n2, a3, n3);
    scan_kernel<<<1, 1024>>>(N);
    fill_all_kernel<<<1024, 256>>>(a1, n1, a2, n2, a3, n3);

    // ---- two GNN layers (largest rel first) ----
    for (int layer = 0; layer < 2; layer++) {
        int hsel = (layer == 0) ? 0 : 1;
        rel_kernel<192, 3, 3><<<(m3 + 63) / 64, 256, SM3>>>(h0, hsel, a3, m3, bi3, bo3, (long long)(n1 + n2) * 64);
        rel_kernel<128, 2, 2><<<(m2 + 63) / 64, 256, SM2>>>(h0, hsel, a2, m2, bi2, bo2, (long long)n1 * 64);
        rel_kernel<64, 1, 1><<<(m1 + 63) / 64, 256, SM1>>>(h0, hsel, a1, m1, bi1, bo1, 0LL);
        agg_kernel<<<(N + 7) / 8, 256>>>(N);
        update_kernel<<<(N + 63) / 64, 256, SMU>>>(h0, hsel, (layer == 0) ? 1 : 2, N, ubi, ubo);
    }

    // ---- readout ----
    bounds_kernel<<<1, 32>>>(tok, B);
    segsum_kernel<<<B, 256>>>();
    heads_kernel<<<B, 64>>>(vWi, vbi, vWo, vbo, dWi, dbi, dWo, dbo, out, B);
}

// round 6
// speedup vs baseline: 1.3328x; 1.0459x over previous
#include <cuda_runtime.h>
#include <math.h>
#include <stdint.h>

// ---------------- static scratch (no allocations allowed) ----------------
#define NMAX   131072
#define TMAX   1700000

__device__ float g_msgs[(size_t)TMAX * 64];
__device__ int   g_colidx[TMAX];
__device__ int   g_counts[NMAX];
__device__ int   g_rowptr[NMAX + 1];
__device__ int   g_cursor[NMAX];
__device__ int   g_bsum[512];
__device__ float g_hA[(size_t)NMAX * 64];
__device__ float g_hB[(size_t)NMAX * 64];
__device__ float g_maxmsg[(size_t)NMAX * 64];
__device__ int   g_bounds[257];
__device__ float g_agg[256 * 64];

// pre-converted tf32 weights
__device__ unsigned g_tfWi1[64 * 64],   g_tfWo1[64 * 64];
__device__ unsigned g_tfWi2[128 * 128], g_tfWo2[128 * 128];
__device__ unsigned g_tfWi3[192 * 192], g_tfWo3[192 * 192];
__device__ unsigned g_tfuWi[128 * 128], g_tfuWo[128 * 64];

// ---------------- math helpers ----------------
__device__ __forceinline__ float mishf(float x) {
    if (x > 20.f) return x;
    float e = __expf(x);
    float n = e * (e + 2.f);
    return x * (n / (n + 2.f));
}

__device__ __forceinline__ void smax_upd(float& m, float& s, float v) {
    if (v > m) { s = s * __expf(12.f * (m - v)) + 1.f; m = v; }
    else       { s += __expf(12.f * (v - m)); }
}

__device__ __forceinline__ unsigned f2tf(float x) {
    unsigned r;
    asm("cvt.rna.tf32.f32 %0, %1;" : "=r"(r) : "f"(x));
    return r;
}

__device__ __forceinline__ void mma8(float* c, unsigned a0, unsigned a1, unsigned a2, unsigned a3,
                                     unsigned b0, unsigned b1) {
    asm volatile(
        "mma.sync.aligned.m16n8k8.row.col.f32.tf32.tf32.f32 "
        "{%0,%1,%2,%3}, {%4,%5,%6,%7}, {%8,%9}, {%0,%1,%2,%3};\n"
        : "+f"(c[0]), "+f"(c[1]), "+f"(c[2]), "+f"(c[3])
        : "r"(a0), "r"(a1), "r"(a2), "r"(a3), "r"(b0), "r"(b1));
}

// ---------------- fused weight pre-conversion ----------------
__global__ void conv_all_kernel(const float* __restrict__ Wi1, const float* __restrict__ Wo1,
                                const float* __restrict__ Wi2, const float* __restrict__ Wo2,
                                const float* __restrict__ Wi3, const float* __restrict__ Wo3,
                                const float* __restrict__ uWi, const float* __restrict__ uWo)
{
    int i = blockIdx.x * blockDim.x + threadIdx.x;
    if (i < 4096)            g_tfWi1[i] = f2tf(Wi1[i]);
    else if (i < 8192)       g_tfWo1[i - 4096] = f2tf(Wo1[i - 4096]);
    else if (i < 24576)      g_tfWi2[i - 8192] = f2tf(Wi2[i - 8192]);
    else if (i < 40960)      g_tfWo2[i - 24576] = f2tf(Wo2[i - 24576]);
    else if (i < 77824)      g_tfWi3[i - 40960] = f2tf(Wi3[i - 40960]);
    else if (i < 114688)     g_tfWo3[i - 77824] = f2tf(Wo3[i - 77824]);
    else if (i < 131072)     g_tfuWi[i - 114688] = f2tf(uWi[i - 114688]);
    else if (i < 139264)     g_tfuWo[i - 131072] = f2tf(uWo[i - 131072]);
}

// ---------------- CSR build ----------------
__global__ void zero_counts_kernel(int n) {
    int i = blockIdx.x * blockDim.x + threadIdx.x;
    if (i < n) g_counts[i] = 0;
}

__global__ void count_all_kernel(const int* __restrict__ a1, int n1,
                                 const int* __restrict__ a2, int n2,
                                 const int* __restrict__ a3, int n3)
{
    int total = n1 + n2 + n3;
    for (int i = blockIdx.x * blockDim.x + threadIdx.x; i < total; i += gridDim.x * blockDim.x) {
        int v = (i < n1) ? a1[i] : (i < n1 + n2) ? a2[i - n1] : a3[i - n1 - n2];
        atomicAdd(&g_counts[v], 1);
    }
}

// phase 1: per-block (1024) exclusive scan, block totals -> g_bsum
__global__ void scan_local_kernel(int n) {
    __shared__ int wsum[32];
    int i = blockIdx.x * 1024 + threadIdx.x;
    int lane = threadIdx.x & 31, wid = threadIdx.x >> 5;
    int v = (i < n) ? g_counts[i] : 0;
    int x = v;
    #pragma unroll
    for (int o = 1; o < 32; o <<= 1) {
        int y = __shfl_up_sync(0xFFFFFFFFu, x, o);
        if (lane >= o) x += y;
    }
    if (lane == 31) wsum[wid] = x;
    __syncthreads();
    if (wid == 0) {
        int s = wsum[lane];
        #pragma unroll
        for (int o = 1; o < 32; o <<= 1) {
            int y = __shfl_up_sync(0xFFFFFFFFu, s, o);
            if (lane >= o) s += y;
        }
        wsum[lane] = s;
    }
    __syncthreads();
    int excl = x - v + ((wid > 0) ? wsum[wid - 1] : 0);
    if (i < n) g_rowptr[i] = excl;
    if (threadIdx.x == 1023) g_bsum[blockIdx.x] = excl + v;
}

// phase 2: exclusive scan of block sums (nb <= 512), 1 block of 512
__global__ void scan_tops_kernel(int nb, int n) {
    __shared__ int sh[512];
    int t = threadIdx.x;
    int v = (t < nb) ? g_bsum[t] : 0;
    sh[t] = v;
    __syncthreads();
    for (int o = 1; o < 512; o <<= 1) {
        int y = (t >= o) ? sh[t - o] : 0;
        __syncthreads();
        sh[t] += y;
        __syncthreads();
    }
    if (t < nb) g_bsum[t] = sh[t] - v;        // exclusive
    if (t == 0) g_rowptr[n] = sh[511];        // grand total
}

// phase 3: add block offsets, init cursors
__global__ void scan_add_kernel(int n) {
    int i = blockIdx.x * blockDim.x + threadIdx.x;
    if (i < n) {
        int r = g_rowptr[i] + g_bsum[i >> 10];
        g_rowptr[i] = r;
        g_cursor[i] = r;
    }
}

__global__ void fill_all_kernel(const int* __restrict__ a1, int n1,
                                const int* __restrict__ a2, int n2,
                                const int* __restrict__ a3, int n3)
{
    int total = n1 + n2 + n3;
    for (int i = blockIdx.x * blockDim.x + threadIdx.x; i < total; i += gridDim.x * blockDim.x) {
        int v = (i < n1) ? a1[i] : (i < n1 + n2) ? a2[i - n1] : a3[i - n1 - n2];
        int pos = atomicAdd(&g_cursor[v], 1);
        g_colidx[pos] = i;
    }
}

// ---------------- relation MLP (TF32 MMA) ----------------
// DB=1: double-buffered weight staging (one sync per chunk). DB=0: single buffer.
template <int S, int A, int R, int DB>
__global__ void __launch_bounds__(256)
rel_kernel(const float* __restrict__ hext, int hsel,
           const int* __restrict__ atoms, int m,
           const float* __restrict__ bi, const float* __restrict__ bo,
           long long outOff)
{
    constexpr int BM  = 64;
    constexpr int NT  = S / 32;
    constexpr int KC  = S / 16;
    constexpr int XST = S + 4;
    constexpr int WST = S + 8;
    constexpr int S4  = S / 4;
    constexpr int PF  = S / 64;

    extern __shared__ unsigned sm[];
    unsigned* xs  = sm;                          // BM * XST (x, later mish(t))
    unsigned* ws0 = xs + BM * XST;               // 16 * WST
    unsigned* ws1 = DB ? (ws0 + 16 * WST) : ws0;
    int* sidx = (int*)(ws0 + (DB ? 32 : 16) * WST);

    const unsigned* Wi = (R == 1) ? g_tfWi1 : (R == 2) ? g_tfWi2 : g_tfWi3;
    const unsigned* Wo = (R == 1) ? g_tfWo1 : (R == 2) ? g_tfWo2 : g_tfWo3;
    const uint4* Wi4 = (const uint4*)Wi;
    const uint4* Wo4 = (const uint4*)Wo;

    const float* h = (hsel == 0) ? hext : ((hsel == 1) ? g_hA : g_hB);
    float* out = g_msgs + outOff;

    const int tid  = threadIdx.x;
    const int lane = tid & 31;
    const int warp = tid >> 5;
    const int rg   = warp & 1;
    const int cg   = warp >> 1;
    const int gid  = lane >> 2;
    const int ctg  = lane & 3;
    const int row0 = blockIdx.x * BM;

    if (tid < BM * A) {
        int t = row0 * A + tid;
        sidx[tid] = (t < m * A) ? atoms[t] : 0;
    }
    __syncthreads();

    const float4* h4 = (const float4*)h;
    #pragma unroll
    for (int v = 0; v < S / 16; v++) {
        int u = tid + v * 256;
        int r = u / S4;
        int rem = u - r * S4;
        int node = sidx[r * A + (rem >> 4)];
        float4 val = h4[(size_t)node * 16 + (rem & 15)];
        ((uint4*)xs)[r * (S4 + 1) + rem] = make_uint4(f2tf(val.x), f2tf(val.y), f2tf(val.z), f2tf(val.w));
    }

    // prologue: stage Wi chunk 0 -> ws0
    {
        uint4 pre[PF];
        #pragma unroll
        for (int v = 0; v < PF; v++) pre[v] = Wi4[tid + v * 256];
        #pragma unroll
        for (int v = 0; v < PF; v++) {
            int u = tid + v * 256;
            int rr = u / S4, c4 = u - rr * S4;
            ((uint4*)ws0)[rr * (WST / 4) + c4] = pre[v];
        }
    }
    __syncthreads();

    float acc[2][NT][4];
    #pragma unroll
    for (int mt = 0; mt < 2; mt++)
        #pragma unroll
        for (int nt = 0; nt < NT; nt++)
            #pragma unroll
            for (int q = 0; q < 4; q++) acc[mt][nt][q] = 0.f;

    const int rb = rg * 32 + gid;
    const int cb = cg * (S / 4);

    unsigned* cur = ws0;
    unsigned* nxt = ws1;

    // ---- GEMM1: acc = x @ Wi ----
    for (int kc = 0; kc < KC; kc++) {
        uint4 pre[PF];
        if (kc + 1 < KC) {
            #pragma unroll
            for (int v = 0; v < PF; v++) pre[v] = Wi4[(kc + 1) * 4 * S + tid + v * 256];
        }
        #pragma unroll
        for (int ks = 0; ks < 2; ks++) {
            int acol = kc * 16 + ks * 8 + ctg;
            unsigned a[2][4];
            #pragma unroll
            for (int mt = 0; mt < 2; mt++) {
                const unsigned* ap = xs + (rb + mt * 16) * XST + acol;
                a[mt][0] = ap[0];
                a[mt][1] = ap[8 * XST];
                a[mt][2] = ap[4];
                a[mt][3] = ap[8 * XST + 4];
            }
            #pragma unroll
            for (int nt = 0; nt < NT; nt++) {
                int bcol = cb + nt * 8 + gid;
                unsigned b0 = cur[(ks * 8 + ctg) * WST + bcol];
                unsigned b1 = cur[(ks * 8 + ctg + 4) * WST + bcol];
                mma8(acc[0][nt], a[0][0], a[0][1], a[0][2], a[0][3], b0, b1);
                mma8(acc[1][nt], a[1][0], a[1][1], a[1][2], a[1][3], b0, b1);
            }
        }
        if (DB) {
            if (kc + 1 < KC) {
                #pragma unroll
                for (int v = 0; v < PF; v++) {
                    int u = tid + v * 256;
                    int rr = u / S4, c4 = u - rr * S4;
                    ((uint4*)nxt)[rr * (WST / 4) + c4] = pre[v];
                }
            }
            __syncthreads();
            unsigned* tmp = cur; cur = nxt; nxt = tmp;
        } else {
            __syncthreads();
            if (kc + 1 < KC) {
                #pragma unroll
                for (int v = 0; v < PF; v++) {
                    int u = tid + v * 256;
                    int rr = u / S4, c4 = u - rr * S4;
                    ((uint4*)cur)[rr * (WST / 4) + c4] = pre[v];
                }
                __syncthreads();
            }
        }
    }

    // ---- bias + mish overwrite xs in place; acc := x + bo (residual) ----
    #pragma unroll
    for (int mt = 0; mt < 2; mt++) {
        int rA = rg * 32 + mt * 16 + gid;
        #pragma unroll
        for (int nt = 0; nt < NT; nt++) {
            int c0 = cb + nt * 8 + 2 * ctg;
            float bi0 = __ldg(&bi[c0]), bi1 = __ldg(&bi[c0 + 1]);
            float bo0 = __ldg(&bo[c0]), bo1 = __ldg(&bo[c0 + 1]);
            unsigned* p0 = &xs[rA * XST + c0];
            unsigned* p1 = &xs[(rA + 8) * XST + c0];
            float x00 = __uint_as_float(p0[0]), x01 = __uint_as_float(p0[1]);
            float x10 = __uint_as_float(p1[0]), x11 = __uint_as_float(p1[1]);
            p0[0] = f2tf(mishf(acc[mt][nt][0] + bi0));
            p0[1] = f2tf(mishf(acc[mt][nt][1] + bi1));
            p1[0] = f2tf(mishf(acc[mt][nt][2] + bi0));
            p1[1] = f2tf(mishf(acc[mt][nt][3] + bi1));
            acc[mt][nt][0] = x00 + bo0;
            acc[mt][nt][1] = x01 + bo1;
            acc[mt][nt][2] = x10 + bo0;
            acc[mt][nt][3] = x11 + bo1;
        }
    }

    // stage Wo chunk 0 -> ws0 (no ws readers alive here; sync below covers mish+ws)
    {
        uint4 pre[PF];
        #pragma unroll
        for (int v = 0; v < PF; v++) pre[v] = Wo4[tid + v * 256];
        #pragma unroll
        for (int v = 0; v < PF; v++) {
            int u = tid + v * 256;
            int rr = u / S4, c4 = u - rr * S4;
            ((uint4*)ws0)[rr * (WST / 4) + c4] = pre[v];
        }
    }
    __syncthreads();

    // ---- GEMM2: acc += mish(.) @ Wo ----
    cur = ws0; nxt = ws1;
    for (int kc = 0; kc < KC; kc++) {
        uint4 pre[PF];
        if (kc + 1 < KC) {
            #pragma unroll
            for (int v = 0; v < PF; v++) pre[v] = Wo4[(kc + 1) * 4 * S + tid + v * 256];
        }
        #pragma unroll
        for (int ks = 0; ks < 2; ks++) {
            int acol = kc * 16 + ks * 8 + ctg;
            unsigned a[2][4];
            #pragma unroll
            for (int mt = 0; mt < 2; mt++) {
                const unsigned* ap = xs + (rb + mt * 16) * XST + acol;
                a[mt][0] = ap[0];
                a[mt][1] = ap[8 * XST];
                a[mt][2] = ap[4];
                a[mt][3] = ap[8 * XST + 4];
            }
            #pragma unroll
            for (int nt = 0; nt < NT; nt++) {
                int bcol = cb + nt * 8 + gid;
                unsigned b0 = cur[(ks * 8 + ctg) * WST + bcol];
                unsigned b1 = cur[(ks * 8 + ctg + 4) * WST + bcol];
                mma8(acc[0][nt], a[0][0], a[0][1], a[0][2], a[0][3], b0, b1);
                mma8(acc[1][nt], a[1][0], a[1][1], a[1][2], a[1][3], b0, b1);
            }
        }
        if (DB) {
            if (kc + 1 < KC) {
                #pragma unroll
                for (int v = 0; v < PF; v++) {
                    int u = tid + v * 256;
                    int rr = u / S4, c4 = u - rr * S4;
                    ((uint4*)nxt)[rr * (WST / 4) + c4] = pre[v];
                }
            }
            __syncthreads();
            unsigned* tmp = cur; cur = nxt; nxt = tmp;
        } else {
            __syncthreads();
            if (kc + 1 < KC) {
                #pragma unroll
                for (int v = 0; v < PF; v++) {
                    int u = tid + v * 256;
                    int rr = u / S4, c4 = u - rr * S4;
                    ((uint4*)cur)[rr * (WST / 4) + c4] = pre[v];
                }
                __syncthreads();
            }
        }
    }

    // ---- store messages ----
    #pragma unroll
    for (int mt = 0; mt < 2; mt++) {
        int rA = row0 + rg * 32 + mt * 16 + gid;
        #pragma unroll
        for (int nt = 0; nt < NT; nt++) {
            int c0 = cb + nt * 8 + 2 * ctg;
            if (rA < m)
                *(float2*)&out[(size_t)rA * S + c0] = make_float2(acc[mt][nt][0], acc[mt][nt][1]);
            if (rA + 8 < m)
                *(float2*)&out[(size_t)(rA + 8) * S + c0] = make_float2(acc[mt][nt][2], acc[mt][nt][3]);
        }
    }
}

// ---------------- smooth-max aggregation ----------------
__global__ void agg_kernel(int n) {
    int w = (blockIdx.x * blockDim.x + threadIdx.x) >> 5;
    if (w >= n) return;
    int lane = threadIdx.x & 31;
    int s = g_rowptr[w], e = g_rowptr[w + 1];

    float m1 = -INFINITY, m2 = -INFINITY, s1 = 0.f, s2 = 0.f;
    int i = s;
    for (; i + 2 <= e; i += 2) {
        int r0 = __ldg(&g_colidx[i]);
        int r1 = __ldg(&g_colidx[i + 1]);
        const float* p0 = g_msgs + (size_t)r0 * 64;
        const float* p1 = g_msgs + (size_t)r1 * 64;
        float a0 = p0[lane], a1 = p0[lane + 32];
        float b0 = p1[lane], b1 = p1[lane + 32];
        smax_upd(m1, s1, a0); smax_upd(m2, s2, a1);
        smax_upd(m1, s1, b0); smax_upd(m2, s2, b1);
    }
    if (i < e) {
        int r0 = __ldg(&g_colidx[i]);
        const float* p0 = g_msgs + (size_t)r0 * 64;
        smax_upd(m1, s1, p0[lane]); smax_upd(m2, s2, p0[lane + 32]);
    }
    if (s == e) { m1 = 0.f; m2 = 0.f; }

    const float inv = 1.f / 12.f;
    g_maxmsg[(size_t)w * 64 + lane]      = __logf(1e-16f + s1) * inv + m1;
    g_maxmsg[(size_t)w * 64 + lane + 32] = __logf(1e-16f + s2) * inv + m2;
}

// ---------------- update MLP (TF32 MMA, aliased buffer) ----------------
__global__ void __launch_bounds__(256)
update_kernel(const float* __restrict__ hext, int hinsel, int houtsel, int n,
              const float* __restrict__ bi, const float* __restrict__ bo)
{
    constexpr int XST = 132;
    constexpr int WST = 136;
    extern __shared__ unsigned sm[];
    unsigned* xs = sm;
    unsigned* ws = xs + 64 * XST;

    const float* hin = (hinsel == 0) ? hext : ((hinsel == 1) ? g_hA : g_hB);
    float* hout = (houtsel == 1) ? g_hA : g_hB;

    const uint4* Wi4 = (const uint4*)g_tfuWi;
    const uint4* Wo4 = (const uint4*)g_tfuWo;

    const int tid  = threadIdx.x;
    const int lane = tid & 31;
    const int warp = tid >> 5;
    const int rg   = warp & 1;
    const int cg   = warp >> 1;
    const int gid  = lane >> 2;
    const int ctg  = lane & 3;
    const int row0 = blockIdx.x * 64;

    const float4* h4 = (const float4*)hin;
    const float4* mm4 = (const float4*)g_maxmsg;
    #pragma unroll
    for (int v = 0; v < 8; v++) {
        int u = tid + v * 256;
        int r = u >> 5, c4 = u & 31;
        float4 val = (c4 < 16) ? mm4[(size_t)(row0 + r) * 16 + c4]
                               : h4[(size_t)(row0 + r) * 16 + (c4 - 16)];
        ((uint4*)xs)[r * 33 + c4] = make_uint4(f2tf(val.x), f2tf(val.y), f2tf(val.z), f2tf(val.w));
    }
    {
        uint4 pre0 = Wi4[tid], pre1 = Wi4[tid + 256];
        ((uint4*)ws)[(tid >> 5) * 34 + (tid & 31)] = pre0;
        int u1 = tid + 256;
        ((uint4*)ws)[(u1 >> 5) * 34 + (u1 & 31)] = pre1;
    }
    __syncthreads();

    const int rb = rg * 32 + gid;

    float acc[2][4][4];
    #pragma unroll
    for (int mt = 0; mt < 2; mt++)
        #pragma unroll
        for (int nt = 0; nt < 4; nt++)
            #pragma unroll
            for (int q = 0; q < 4; q++) acc[mt][nt][q] = 0.f;

    for (int kc = 0; kc < 8; kc++) {
        uint4 pre0, pre1;
        if (kc + 1 < 8) {
            pre0 = Wi4[(kc + 1) * 512 + tid];
            pre1 = Wi4[(kc + 1) * 512 + tid + 256];
        }
        #pragma unroll
        for (int ks = 0; ks < 2; ks++) {
            int acol = kc * 16 + ks * 8 + ctg;
            unsigned a[2][4];
            #pragma unroll
            for (int mt = 0; mt < 2; mt++) {
                const unsigned* ap = xs + (rb + mt * 16) * XST + acol;
                a[mt][0] = ap[0];
                a[mt][1] = ap[8 * XST];
                a[mt][2] = ap[4];
                a[mt][3] = ap[8 * XST + 4];
            }
            #pragma unroll
            for (int nt = 0; nt < 4; nt++) {
                int bcol = cg * 32 + nt * 8 + gid;
                unsigned b0 = ws[(ks * 8 + ctg) * WST + bcol];
                unsigned b1 = ws[(ks * 8 + ctg + 4) * WST + bcol];
                mma8(acc[0][nt], a[0][0], a[0][1], a[0][2], a[0][3], b0, b1);
                mma8(acc[1][nt], a[1][0], a[1][1], a[1][2], a[1][3], b0, b1);
            }
        }
        __syncthreads();
        if (kc + 1 < 8) {
            ((uint4*)ws)[(tid >> 5) * 34 + (tid & 31)] = pre0;
            int u1 = tid + 256;
            ((uint4*)ws)[(u1 >> 5) * 34 + (u1 & 31)] = pre1;
            __syncthreads();
        }
    }

    float acc2[2][2][4];
    #pragma unroll
    for (int mt = 0; mt < 2; mt++) {
        int rA = rg * 32 + mt * 16 + gid;
        #pragma unroll
        for (int nt = 0; nt < 2; nt++) {
            int c0 = cg * 16 + nt * 8 + 2 * ctg;
            float bo0 = __ldg(&bo[c0]), bo1 = __ldg(&bo[c0 + 1]);
            acc2[mt][nt][0] = __uint_as_float(xs[rA * XST + 64 + c0]) + bo0;
            acc2[mt][nt][1] = __uint_as_float(xs[rA * XST + 64 + c0 + 1]) + bo1;
            acc2[mt][nt][2] = __uint_as_float(xs[(rA + 8) * XST + 64 + c0]) + bo0;
            acc2[mt][nt][3] = __uint_as_float(xs[(rA + 8) * XST + 64 + c0 + 1]) + bo1;
        }
    }
    __syncthreads();

    #pragma unroll
    for (int mt = 0; mt < 2; mt++) {
        int rA = rg * 32 + mt * 16 + gid;
        #pragma unroll
        for (int nt = 0; nt < 4; nt++) {
            int c0 = cg * 32 + nt * 8 + 2 * ctg;
            float bi0 = __ldg(&bi[c0]), bi1 = __ldg(&bi[c0 + 1]);
            xs[rA * XST + c0]           = f2tf(mishf(acc[mt][nt][0] + bi0));
            xs[rA * XST + c0 + 1]       = f2tf(mishf(acc[mt][nt][1] + bi1));
            xs[(rA + 8) * XST + c0]     = f2tf(mishf(acc[mt][nt][2] + bi0));
            xs[(rA + 8) * XST + c0 + 1] = f2tf(mishf(acc[mt][nt][3] + bi1));
        }
    }

    {
        uint4 preW = Wo4[tid];
        __syncthreads();
        ((uint4*)ws)[(tid >> 4) * 34 + (tid & 15)] = preW;
    }
    __syncthreads();

    for (int kc = 0; kc < 8; kc++) {
        uint4 pre;
        if (kc + 1 < 8) pre = Wo4[(kc + 1) * 256 + tid];
        #pragma unroll
        for (int ks = 0; ks < 2; ks++) {
            int acol = kc * 16 + ks * 8 + ctg;
            unsigned a[2][4];
            #pragma unroll
            for (int mt = 0; mt < 2; mt++) {
                const unsigned* ap = xs + (rb + mt * 16) * XST + acol;
                a[mt][0] = ap[0];
                a[mt][1] = ap[8 * XST];
                a[mt][2] = ap[4];
                a[mt][3] = ap[8 * XST + 4];
            }
            #pragma unroll
            for (int nt = 0; nt < 2; nt++) {
                int bcol = cg * 16 + nt * 8 + gid;
                unsigned b0 = ws[(ks * 8 + ctg) * WST + bcol];
                unsigned b1 = ws[(ks * 8 + ctg + 4) * WST + bcol];
                mma8(acc2[0][nt], a[0][0], a[0][1], a[0][2], a[0][3], b0, b1);
                mma8(acc2[1][nt], a[1][0], a[1][1], a[1][2], a[1][3], b0, b1);
            }
        }
        __syncthreads();
        if (kc + 1 < 8) {
            ((uint4*)ws)[(tid >> 4) * 34 + (tid & 15)] = pre;
            __syncthreads();
        }
    }

    #pragma unroll
    for (int mt = 0; mt < 2; mt++) {
        int rA = row0 + rg * 32 + mt * 16 + gid;
        #pragma unroll
        for (int nt = 0; nt < 2; nt++) {
            int c0 = cg * 16 + nt * 8 + 2 * ctg;
            if (rA < n)
                *(float2*)&hout[(size_t)rA * 64 + c0] = make_float2(acc2[mt][nt][0], acc2[mt][nt][1]);
            if (rA + 8 < n)
                *(float2*)&hout[(size_t)(rA + 8) * 64 + c0] = make_float2(acc2[mt][nt][2], acc2[mt][nt][3]);
        }
    }
}

// ---------------- readout ----------------
__global__ void bounds_kernel(const int* __restrict__ tok, int B) {
    if (threadIdx.x == 0) {
        int c = 0;
        g_bounds[0] = 0;
        for (int i = 0; i < B; i++) { c += tok[i]; g_bounds[i + 1] = c; }
    }
}

__global__ void segsum_kernel() {
    int b = blockIdx.x;
    int s = g_bounds[b], e = g_bounds[b + 1];
    int f = threadIdx.x & 63, g = threadIdx.x >> 6;
    float a = 0.f;
    for (int r = s + g; r < e; r += 4) a += g_hB[(size_t)r * 64 + f];
    __shared__ float red[256];
    red[threadIdx.x] = a;
    __syncthreads();
    if (g == 0) g_agg[b * 64 + f] = red[f] + red[64 + f] + red[128 + f] + red[192 + f];
}

__global__ void heads_kernel(const float* __restrict__ vWi, const float* __restrict__ vbi,
                             const float* __restrict__ vWo, const float* __restrict__ vbo,
                             const float* __restrict__ dWi, const float* __restrict__ dbi,
                             const float* __restrict__ dWo, const float* __restrict__ dbo,
                             float* __restrict__ out, int B)
{
    int b = blockIdx.x, o = threadIdx.x;
    __shared__ float a[64];
    __shared__ float red[64];
    a[o] = g_agg[b * 64 + o];
    __syncthreads();

    float t = vbi[o];
    for (int i = 0; i < 64; i++) t = fmaf(a[i], vWi[i * 64 + o], t);
    red[o] = mishf(t) * vWo[o];
    __syncthreads();
    for (int s = 32; s > 0; s >>= 1) {
        if (o < s) red[o] += red[o + s];
        __syncthreads();
    }
    if (o == 0) out[b] = red[0] + vbo[0];
    __syncthreads();

    t = dbi[o];
    for (int i = 0; i < 64; i++) t = fmaf(a[i], dWi[i * 64 + o], t);
    red[o] = mishf(t) * dWo[o];
    __syncthreads();
    for (int s = 32; s > 0; s >>= 1) {
        if (o < s) red[o] += red[o + s];
        __syncthreads();
    }
    if (o == 0) out[B + b] = red[0] + dbo[0];
}

// ---------------- host launch ----------------
static inline int smem_rel(int S, int A, int db) {
    return (64 * (S + 4) + (db ? 32 : 16) * (S + 8)) * 4 + 64 * A * 4;
}

extern "C" void kernel_launch(void* const* d_in, const int* in_sizes, int n_in,
                              void* d_out, int out_size)
{
    if (n_in < 29) return;
    const float* h0  = (const float*)d_in[0];
    const int*   a1  = (const int*)d_in[1];  int n1 = in_sizes[1];
    const int*   a2  = (const int*)d_in[2];  int n2 = in_sizes[2];
    const int*   a3  = (const int*)d_in[3];  int n3 = in_sizes[3];
    const int*   tok = (const int*)d_in[4];  int B  = in_sizes[4];
    const float* Wi1 = (const float*)d_in[5],  *bi1 = (const float*)d_in[6];
    const float* Wo1 = (const float*)d_in[7],  *bo1 = (const float*)d_in[8];
    const float* Wi2 = (const float*)d_in[9],  *bi2 = (const float*)d_in[10];
    const float* Wo2 = (const float*)d_in[11], *bo2 = (const float*)d_in[12];
    const float* Wi3 = (const float*)d_in[13], *bi3 = (const float*)d_in[14];
    const float* Wo3 = (const float*)d_in[15], *bo3 = (const float*)d_in[16];
    const float* uWi = (const float*)d_in[17], *ubi = (const float*)d_in[18];
    const float* uWo = (const float*)d_in[19], *ubo = (const float*)d_in[20];
    const float* vWi = (const float*)d_in[21], *vbi = (const float*)d_in[22];
    const float* vWo = (const float*)d_in[23], *vbo = (const float*)d_in[24];
    const float* dWi = (const float*)d_in[25], *dbi = (const float*)d_in[26];
    const float* dWo = (const float*)d_in[27], *dbo = (const float*)d_in[28];
    float* out = (float*)d_out;

    int N = in_sizes[0] / 64;
    int m1 = n1, m2 = n2 / 2, m3 = n3 / 3;
    int nb = (N + 1023) / 1024;

    const int SM1 = smem_rel(64, 1, 1);
    const int SM2 = smem_rel(128, 2, 0);
    const int SM3 = smem_rel(192, 3, 1);
    const int SMU = (64 * 132 + 16 * 136) * 4;

    cudaFuncSetAttribute(rel_kernel<64, 1, 1, 1>,  cudaFuncAttributeMaxDynamicSharedMemorySize, SM1);
    cudaFuncSetAttribute(rel_kernel<128, 2, 2, 0>, cudaFuncAttributeMaxDynamicSharedMemorySize, SM2);
    cudaFuncSetAttribute(rel_kernel<192, 3, 3, 1>, cudaFuncAttributeMaxDynamicSharedMemorySize, SM3);
    cudaFuncSetAttribute(update_kernel,            cudaFuncAttributeMaxDynamicSharedMemorySize, SMU);

    // prologue: 5 launches, then rel<192> is launch index 5 (ncu -s 5 -c 1 target)
    conv_all_kernel<<<(139264 + 255) / 256, 256>>>(Wi1, Wo1, Wi2, Wo2, Wi3, Wo3, uWi, uWo);
    zero_counts_kernel<<<(N + 255) / 256, 256>>>(N);
    count_all_kernel<<<1024, 256>>>(a1, n1, a2, n2, a3, n3);
    scan_local_kernel<<<nb, 1024>>>(N);
    scan_tops_kernel<<<1, 512>>>(nb, N);

    // layer 0, relation kernels don't need the CSR
    rel_kernel<192, 3, 3, 1><<<(m3 + 63) / 64, 256, SM3>>>(h0, 0, a3, m3, bi3, bo3, (long long)(n1 + n2) * 64);

    scan_add_kernel<<<(N + 255) / 256, 256>>>(N);
    fill_all_kernel<<<1024, 256>>>(a1, n1, a2, n2, a3, n3);

    rel_kernel<128, 2, 2, 0><<<(m2 + 63) / 64, 256, SM2>>>(h0, 0, a2, m2, bi2, bo2, (long long)n1 * 64);
    rel_kernel<64, 1, 1, 1><<<(m1 + 63) / 64, 256, SM1>>>(h0, 0, a1, m1, bi1, bo1, 0LL);
    agg_kernel<<<(N + 7) / 8, 256>>>(N);
    update_kernel<<<(N + 63) / 64, 256, SMU>>>(h0, 0, 1, N, ubi, ubo);

    // layer 1
    rel_kernel<192, 3, 3, 1><<<(m3 + 63) / 64, 256, SM3>>>(h0, 1, a3, m3, bi3, bo3, (long long)(n1 + n2) * 64);
    rel_kernel<128, 2, 2, 0><<<(m2 + 63) / 64, 256, SM2>>>(h0, 1, a2, m2, bi2, bo2, (long long)n1 * 64);
    rel_kernel<64, 1, 1, 1><<<(m1 + 63) / 64, 256, SM1>>>(h0, 1, a1, m1, bi1, bo1, 0LL);
    agg_kernel<<<(N + 7) / 8, 256>>>(N);
    update_kernel<<<(N + 63) / 64, 256, SMU>>>(h0, 1, 2, N, ubi, ubo);

    // readout
    bounds_kernel<<<1, 32>>>(tok, B);
    segsum_kernel<<<B, 256>>>();
    heads_kernel<<<B, 64>>>(vWi, vbi, vWo, vbo, dWi, dbi, dWo, dbo, out, B);
}

// round 7
// speedup vs baseline: 1.5344x; 1.1513x over previous
#include <cuda_runtime.h>
#include <math.h>
#include <stdint.h>

// ---------------- static scratch (no allocations allowed) ----------------
#define NMAX   131072
#define TMAX   1700000

__device__ float g_msgs[(size_t)TMAX * 64];     // r2|r3 messages
__device__ float g_msg1[(size_t)NMAX * 64];     // per-node r1 messages
__device__ int   g_colidx[TMAX];
__device__ int   g_counts[NMAX];                // r2+r3 counts
__device__ int   g_cnt1[NMAX];                  // r1 multiplicities
__device__ int   g_rowptr[NMAX + 1];
__device__ int   g_cursor[NMAX];
__device__ int   g_bsum[512];
__device__ float g_hA[(size_t)NMAX * 64];
__device__ float g_hB[(size_t)NMAX * 64];
__device__ float g_maxmsg[(size_t)NMAX * 64];
__device__ int   g_bounds[257];
__device__ float g_agg[256 * 64];

// pre-converted tf32 weights
__device__ unsigned g_tfWi1[64 * 64],   g_tfWo1[64 * 64];
__device__ unsigned g_tfWi2[128 * 128], g_tfWo2[128 * 128];
__device__ unsigned g_tfWi3[192 * 192], g_tfWo3[192 * 192];
__device__ unsigned g_tfuWi[128 * 128], g_tfuWo[128 * 64];

// ---------------- math helpers ----------------
__device__ __forceinline__ float mishf(float x) {
    if (x > 20.f) return x;
    float e = __expf(x);
    float n = e * (e + 2.f);
    return x * (n / (n + 2.f));
}

__device__ __forceinline__ void smax_upd(float& m, float& s, float v) {
    if (v > m) { s = s * __expf(12.f * (m - v)) + 1.f; m = v; }
    else       { s += __expf(12.f * (v - m)); }
}

__device__ __forceinline__ unsigned f2tf(float x) {
    unsigned r;
    asm("cvt.rna.tf32.f32 %0, %1;" : "=r"(r) : "f"(x));
    return r;
}

__device__ __forceinline__ void mma8(float* c, unsigned a0, unsigned a1, unsigned a2, unsigned a3,
                                     unsigned b0, unsigned b1) {
    asm volatile(
        "mma.sync.aligned.m16n8k8.row.col.f32.tf32.tf32.f32 "
        "{%0,%1,%2,%3}, {%4,%5,%6,%7}, {%8,%9}, {%0,%1,%2,%3};\n"
        : "+f"(c[0]), "+f"(c[1]), "+f"(c[2]), "+f"(c[3])
        : "r"(a0), "r"(a1), "r"(a2), "r"(a3), "r"(b0), "r"(b1));
}

// ---------------- fused weight pre-conversion ----------------
__global__ void conv_all_kernel(const float* __restrict__ Wi1, const float* __restrict__ Wo1,
                                const float* __restrict__ Wi2, const float* __restrict__ Wo2,
                                const float* __restrict__ Wi3, const float* __restrict__ Wo3,
                                const float* __restrict__ uWi, const float* __restrict__ uWo)
{
    int i = blockIdx.x * blockDim.x + threadIdx.x;
    if (i < 4096)            g_tfWi1[i] = f2tf(Wi1[i]);
    else if (i < 8192)       g_tfWo1[i - 4096] = f2tf(Wo1[i - 4096]);
    else if (i < 24576)      g_tfWi2[i - 8192] = f2tf(Wi2[i - 8192]);
    else if (i < 40960)      g_tfWo2[i - 24576] = f2tf(Wo2[i - 24576]);
    else if (i < 77824)      g_tfWi3[i - 40960] = f2tf(Wi3[i - 40960]);
    else if (i < 114688)     g_tfWo3[i - 77824] = f2tf(Wo3[i - 77824]);
    else if (i < 131072)     g_tfuWi[i - 114688] = f2tf(uWi[i - 114688]);
    else if (i < 139264)     g_tfuWo[i - 131072] = f2tf(uWo[i - 131072]);
}

// ---------------- CSR build (r2/r3 only; r1 -> multiplicity counts) ----------------
__global__ void zero_counts_kernel(int n) {
    int i = blockIdx.x * blockDim.x + threadIdx.x;
    if (i < n) { g_counts[i] = 0; g_cnt1[i] = 0; }
}

__global__ void count_all_kernel(const int* __restrict__ a1, int n1,
                                 const int* __restrict__ a2, int n2,
                                 const int* __restrict__ a3, int n3)
{
    int total = n1 + n2 + n3;
    for (int i = blockIdx.x * blockDim.x + threadIdx.x; i < total; i += gridDim.x * blockDim.x) {
        if (i < n2)            atomicAdd(&g_counts[a2[i]], 1);
        else if (i < n2 + n3)  atomicAdd(&g_counts[a3[i - n2]], 1);
        else                   atomicAdd(&g_cnt1[a1[i - n2 - n3]], 1);
    }
}

// phase 1: per-block (1024) exclusive scan, block totals -> g_bsum
__global__ void scan_local_kernel(int n) {
    __shared__ int wsum[32];
    int i = blockIdx.x * 1024 + threadIdx.x;
    int lane = threadIdx.x & 31, wid = threadIdx.x >> 5;
    int v = (i < n) ? g_counts[i] : 0;
    int x = v;
    #pragma unroll
    for (int o = 1; o < 32; o <<= 1) {
        int y = __shfl_up_sync(0xFFFFFFFFu, x, o);
        if (lane >= o) x += y;
    }
    if (lane == 31) wsum[wid] = x;
    __syncthreads();
    if (wid == 0) {
        int s = wsum[lane];
        #pragma unroll
        for (int o = 1; o < 32; o <<= 1) {
            int y = __shfl_up_sync(0xFFFFFFFFu, s, o);
            if (lane >= o) s += y;
        }
        wsum[lane] = s;
    }
    __syncthreads();
    int excl = x - v + ((wid > 0) ? wsum[wid - 1] : 0);
    if (i < n) g_rowptr[i] = excl;
    if (threadIdx.x == 1023) g_bsum[blockIdx.x] = excl + v;
}

// phase 2: exclusive scan of block sums
__global__ void scan_tops_kernel(int nb, int n) {
    __shared__ int sh[512];
    int t = threadIdx.x;
    int v = (t < nb) ? g_bsum[t] : 0;
    sh[t] = v;
    __syncthreads();
    for (int o = 1; o < 512; o <<= 1) {
        int y = (t >= o) ? sh[t - o] : 0;
        __syncthreads();
        sh[t] += y;
        __syncthreads();
    }
    if (t < nb) g_bsum[t] = sh[t] - v;
    if (t == 0) g_rowptr[n] = sh[511];
}

// phase 3: add block offsets, init cursors
__global__ void scan_add_kernel(int n) {
    int i = blockIdx.x * blockDim.x + threadIdx.x;
    if (i < n) {
        int r = g_rowptr[i] + g_bsum[i >> 10];
        g_rowptr[i] = r;
        g_cursor[i] = r;
    }
}

__global__ void fill_all_kernel(const int* __restrict__ a2, int n2,
                                const int* __restrict__ a3, int n3)
{
    int total = n2 + n3;
    for (int i = blockIdx.x * blockDim.x + threadIdx.x; i < total; i += gridDim.x * blockDim.x) {
        int v = (i < n2) ? a2[i] : a3[i - n2];
        int pos = atomicAdd(&g_cursor[v], 1);
        g_colidx[pos] = i;   // r2 rows [0,n2), r3 rows [n2, n2+n3)
    }
}

// ---------------- relation MLP (TF32 MMA) ----------------
// IDENT=1: identity gather (row index == node id), output -> g_msg1.
template <int S, int A, int R, int DB, int IDENT>
__global__ void __launch_bounds__(256)
rel_kernel(const float* __restrict__ hext, int hsel,
           const int* __restrict__ atoms, int m,
           const float* __restrict__ bi, const float* __restrict__ bo,
           long long outOff)
{
    constexpr int BM  = 64;
    constexpr int NT  = S / 32;
    constexpr int KC  = S / 16;
    constexpr int XST = S + 4;
    constexpr int WST = S + 8;
    constexpr int S4  = S / 4;
    constexpr int PF  = S / 64;

    extern __shared__ unsigned sm[];
    unsigned* xs  = sm;                          // BM * XST (x, later mish(t))
    unsigned* ws0 = xs + BM * XST;               // 16 * WST
    unsigned* ws1 = DB ? (ws0 + 16 * WST) : ws0;
    int* sidx = (int*)(ws0 + (DB ? 32 : 16) * WST);

    const unsigned* Wi = (R == 1) ? g_tfWi1 : (R == 2) ? g_tfWi2 : g_tfWi3;
    const unsigned* Wo = (R == 1) ? g_tfWo1 : (R == 2) ? g_tfWo2 : g_tfWo3;
    const uint4* Wi4 = (const uint4*)Wi;
    const uint4* Wo4 = (const uint4*)Wo;

    const float* h = (hsel == 0) ? hext : ((hsel == 1) ? g_hA : g_hB);
    float* out = IDENT ? g_msg1 : (g_msgs + outOff);

    const int tid  = threadIdx.x;
    const int lane = tid & 31;
    const int warp = tid >> 5;
    const int rg   = warp & 1;
    const int cg   = warp >> 1;
    const int gid  = lane >> 2;
    const int ctg  = lane & 3;
    const int row0 = blockIdx.x * BM;

    if (!IDENT) {
        if (tid < BM * A) {
            int t = row0 * A + tid;
            sidx[tid] = (t < m * A) ? atoms[t] : 0;
        }
        __syncthreads();
    }

    const float4* h4 = (const float4*)h;
    #pragma unroll
    for (int v = 0; v < S / 16; v++) {
        int u = tid + v * 256;
        int r = u / S4;
        int rem = u - r * S4;
        int node;
        if (IDENT) { node = row0 + r; if (node >= m) node = 0; }
        else       { node = sidx[r * A + (rem >> 4)]; }
        float4 val = h4[(size_t)node * 16 + (rem & 15)];
        ((uint4*)xs)[r * (S4 + 1) + rem] = make_uint4(f2tf(val.x), f2tf(val.y), f2tf(val.z), f2tf(val.w));
    }

    // prologue: stage Wi chunk 0 -> ws0
    {
        uint4 pre[PF];
        #pragma unroll
        for (int v = 0; v < PF; v++) pre[v] = Wi4[tid + v * 256];
        #pragma unroll
        for (int v = 0; v < PF; v++) {
            int u = tid + v * 256;
            int rr = u / S4, c4 = u - rr * S4;
            ((uint4*)ws0)[rr * (WST / 4) + c4] = pre[v];
        }
    }
    __syncthreads();

    float acc[2][NT][4];
    #pragma unroll
    for (int mt = 0; mt < 2; mt++)
        #pragma unroll
        for (int nt = 0; nt < NT; nt++)
            #pragma unroll
            for (int q = 0; q < 4; q++) acc[mt][nt][q] = 0.f;

    const int rb = rg * 32 + gid;
    const int cb = cg * (S / 4);

    unsigned* cur = ws0;
    unsigned* nxt = ws1;

    // ---- GEMM1: acc = x @ Wi ----
    for (int kc = 0; kc < KC; kc++) {
        uint4 pre[PF];
        if (kc + 1 < KC) {
            #pragma unroll
            for (int v = 0; v < PF; v++) pre[v] = Wi4[(kc + 1) * 4 * S + tid + v * 256];
        }
        #pragma unroll
        for (int ks = 0; ks < 2; ks++) {
            int acol = kc * 16 + ks * 8 + ctg;
            unsigned a[2][4];
            #pragma unroll
            for (int mt = 0; mt < 2; mt++) {
                const unsigned* ap = xs + (rb + mt * 16) * XST + acol;
                a[mt][0] = ap[0];
                a[mt][1] = ap[8 * XST];
                a[mt][2] = ap[4];
                a[mt][3] = ap[8 * XST + 4];
            }
            #pragma unroll
            for (int nt = 0; nt < NT; nt++) {
                int bcol = cb + nt * 8 + gid;
                unsigned b0 = cur[(ks * 8 + ctg) * WST + bcol];
                unsigned b1 = cur[(ks * 8 + ctg + 4) * WST + bcol];
                mma8(acc[0][nt], a[0][0], a[0][1], a[0][2], a[0][3], b0, b1);
                mma8(acc[1][nt], a[1][0], a[1][1], a[1][2], a[1][3], b0, b1);
            }
        }
        if (DB) {
            if (kc + 1 < KC) {
                #pragma unroll
                for (int v = 0; v < PF; v++) {
                    int u = tid + v * 256;
                    int rr = u / S4, c4 = u - rr * S4;
                    ((uint4*)nxt)[rr * (WST / 4) + c4] = pre[v];
                }
            }
            __syncthreads();
            unsigned* tmp = cur; cur = nxt; nxt = tmp;
        } else {
            __syncthreads();
            if (kc + 1 < KC) {
                #pragma unroll
                for (int v = 0; v < PF; v++) {
                    int u = tid + v * 256;
                    int rr = u / S4, c4 = u - rr * S4;
                    ((uint4*)cur)[rr * (WST / 4) + c4] = pre[v];
                }
                __syncthreads();
            }
        }
    }

    // ---- bias + mish overwrite xs in place; acc := x + bo (residual) ----
    #pragma unroll
    for (int mt = 0; mt < 2; mt++) {
        int rA = rg * 32 + mt * 16 + gid;
        #pragma unroll
        for (int nt = 0; nt < NT; nt++) {
            int c0 = cb + nt * 8 + 2 * ctg;
            float bi0 = __ldg(&bi[c0]), bi1 = __ldg(&bi[c0 + 1]);
            float bo0 = __ldg(&bo[c0]), bo1 = __ldg(&bo[c0 + 1]);
            unsigned* p0 = &xs[rA * XST + c0];
            unsigned* p1 = &xs[(rA + 8) * XST + c0];
            float x00 = __uint_as_float(p0[0]), x01 = __uint_as_float(p0[1]);
            float x10 = __uint_as_float(p1[0]), x11 = __uint_as_float(p1[1]);
            p0[0] = f2tf(mishf(acc[mt][nt][0] + bi0));
            p0[1] = f2tf(mishf(acc[mt][nt][1] + bi1));
            p1[0] = f2tf(mishf(acc[mt][nt][2] + bi0));
            p1[1] = f2tf(mishf(acc[mt][nt][3] + bi1));
            acc[mt][nt][0] = x00 + bo0;
            acc[mt][nt][1] = x01 + bo1;
            acc[mt][nt][2] = x10 + bo0;
            acc[mt][nt][3] = x11 + bo1;
        }
    }

    // stage Wo chunk 0 -> ws0
    {
        uint4 pre[PF];
        #pragma unroll
        for (int v = 0; v < PF; v++) pre[v] = Wo4[tid + v * 256];
        #pragma unroll
        for (int v = 0; v < PF; v++) {
            int u = tid + v * 256;
            int rr = u / S4, c4 = u - rr * S4;
            ((uint4*)ws0)[rr * (WST / 4) + c4] = pre[v];
        }
    }
    __syncthreads();

    // ---- GEMM2: acc += mish(.) @ Wo ----
    cur = ws0; nxt = ws1;
    for (int kc = 0; kc < KC; kc++) {
        uint4 pre[PF];
        if (kc + 1 < KC) {
            #pragma unroll
            for (int v = 0; v < PF; v++) pre[v] = Wo4[(kc + 1) * 4 * S + tid + v * 256];
        }
        #pragma unroll
        for (int ks = 0; ks < 2; ks++) {
            int acol = kc * 16 + ks * 8 + ctg;
            unsigned a[2][4];
            #pragma unroll
            for (int mt = 0; mt < 2; mt++) {
                const unsigned* ap = xs + (rb + mt * 16) * XST + acol;
                a[mt][0] = ap[0];
                a[mt][1] = ap[8 * XST];
                a[mt][2] = ap[4];
                a[mt][3] = ap[8 * XST + 4];
            }
            #pragma unroll
            for (int nt = 0; nt < NT; nt++) {
                int bcol = cb + nt * 8 + gid;
                unsigned b0 = cur[(ks * 8 + ctg) * WST + bcol];
                unsigned b1 = cur[(ks * 8 + ctg + 4) * WST + bcol];
                mma8(acc[0][nt], a[0][0], a[0][1], a[0][2], a[0][3], b0, b1);
                mma8(acc[1][nt], a[1][0], a[1][1], a[1][2], a[1][3], b0, b1);
            }
        }
        if (DB) {
            if (kc + 1 < KC) {
                #pragma unroll
                for (int v = 0; v < PF; v++) {
                    int u = tid + v * 256;
                    int rr = u / S4, c4 = u - rr * S4;
                    ((uint4*)nxt)[rr * (WST / 4) + c4] = pre[v];
                }
            }
            __syncthreads();
            unsigned* tmp = cur; cur = nxt; nxt = tmp;
        } else {
            __syncthreads();
            if (kc + 1 < KC) {
                #pragma unroll
                for (int v = 0; v < PF; v++) {
                    int u = tid + v * 256;
                    int rr = u / S4, c4 = u - rr * S4;
                    ((uint4*)cur)[rr * (WST / 4) + c4] = pre[v];
                }
                __syncthreads();
            }
        }
    }

    // ---- store messages (streaming: read-once data) ----
    #pragma unroll
    for (int mt = 0; mt < 2; mt++) {
        int rA = row0 + rg * 32 + mt * 16 + gid;
        #pragma unroll
        for (int nt = 0; nt < NT; nt++) {
            int c0 = cb + nt * 8 + 2 * ctg;
            if (rA < m)
                __stcs((float2*)&out[(size_t)rA * S + c0], make_float2(acc[mt][nt][0], acc[mt][nt][1]));
            if (rA + 8 < m)
                __stcs((float2*)&out[(size_t)(rA + 8) * S + c0], make_float2(acc[mt][nt][2], acc[mt][nt][3]));
        }
    }
}

// ---------------- smooth-max aggregation ----------------
__global__ void agg_kernel(int n) {
    int w = (blockIdx.x * blockDim.x + threadIdx.x) >> 5;
    if (w >= n) return;
    int lane = threadIdx.x & 31;
    int s = g_rowptr[w], e = g_rowptr[w + 1];

    float m1 = -INFINITY, m2 = -INFINITY, s1 = 0.f, s2 = 0.f;
    int i = s;
    for (; i + 4 <= e; i += 4) {
        int c0 = __ldg(&g_colidx[i]);
        int c1 = __ldg(&g_colidx[i + 1]);
        int c2 = __ldg(&g_colidx[i + 2]);
        int c3 = __ldg(&g_colidx[i + 3]);
        const float* p0 = g_msgs + (size_t)c0 * 64;
        const float* p1 = g_msgs + (size_t)c1 * 64;
        const float* p2 = g_msgs + (size_t)c2 * 64;
        const float* p3 = g_msgs + (size_t)c3 * 64;
        float a0 = __ldcs(p0 + lane), b0 = __ldcs(p0 + lane + 32);
        float a1 = __ldcs(p1 + lane), b1 = __ldcs(p1 + lane + 32);
        float a2 = __ldcs(p2 + lane), b2 = __ldcs(p2 + lane + 32);
        float a3 = __ldcs(p3 + lane), b3 = __ldcs(p3 + lane + 32);
        smax_upd(m1, s1, a0); smax_upd(m2, s2, b0);
        smax_upd(m1, s1, a1); smax_upd(m2, s2, b1);
        smax_upd(m1, s1, a2); smax_upd(m2, s2, b2);
        smax_upd(m1, s1, a3); smax_upd(m2, s2, b3);
    }
    for (; i < e; i++) {
        int c0 = __ldg(&g_colidx[i]);
        const float* p0 = g_msgs + (size_t)c0 * 64;
        smax_upd(m1, s1, __ldcs(p0 + lane));
        smax_upd(m2, s2, __ldcs(p0 + lane + 32));
    }

    // r1: k identical copies of y1(w)
    int k = g_cnt1[w];
    if (k > 0) {
        float kf = (float)k;
        const float* py = g_msg1 + (size_t)w * 64;
        float y1 = py[lane], y2 = py[lane + 32];
        if (y1 > m1) { s1 = s1 * __expf(12.f * (m1 - y1)) + kf; m1 = y1; }
        else         { s1 += kf * __expf(12.f * (y1 - m1)); }
        if (y2 > m2) { s2 = s2 * __expf(12.f * (m2 - y2)) + kf; m2 = y2; }
        else         { s2 += kf * __expf(12.f * (y2 - m2)); }
    }

    if (s == e && k == 0) { m1 = 0.f; m2 = 0.f; }   // empty node

    const float inv = 1.f / 12.f;
    g_maxmsg[(size_t)w * 64 + lane]      = __logf(1e-16f + s1) * inv + m1;
    g_maxmsg[(size_t)w * 64 + lane + 32] = __logf(1e-16f + s2) * inv + m2;
}

// ---------------- update MLP (TF32 MMA, aliased buffer) ----------------
__global__ void __launch_bounds__(256)
update_kernel(const float* __restrict__ hext, int hinsel, int houtsel, int n,
              const float* __restrict__ bi, const float* __restrict__ bo)
{
    constexpr int XST = 132;
    constexpr int WST = 136;
    extern __shared__ unsigned sm[];
    unsigned* xs = sm;
    unsigned* ws = xs + 64 * XST;

    const float* hin = (hinsel == 0) ? hext : ((hinsel == 1) ? g_hA : g_hB);
    float* hout = (houtsel == 1) ? g_hA : g_hB;

    const uint4* Wi4 = (const uint4*)g_tfuWi;
    const uint4* Wo4 = (const uint4*)g_tfuWo;

    const int tid  = threadIdx.x;
    const int lane = tid & 31;
    const int warp = tid >> 5;
    const int rg   = warp & 1;
    const int cg   = warp >> 1;
    const int gid  = lane >> 2;
    const int ctg  = lane & 3;
    const int row0 = blockIdx.x * 64;

    const float4* h4 = (const float4*)hin;
    const float4* mm4 = (const float4*)g_maxmsg;
    #pragma unroll
    for (int v = 0; v < 8; v++) {
        int u = tid + v * 256;
        int r = u >> 5, c4 = u & 31;
        float4 val = (c4 < 16) ? mm4[(size_t)(row0 + r) * 16 + c4]
                               : h4[(size_t)(row0 + r) * 16 + (c4 - 16)];
        ((uint4*)xs)[r * 33 + c4] = make_uint4(f2tf(val.x), f2tf(val.y), f2tf(val.z), f2tf(val.w));
    }
    {
        uint4 pre0 = Wi4[tid], pre1 = Wi4[tid + 256];
        ((uint4*)ws)[(tid >> 5) * 34 + (tid & 31)] = pre0;
        int u1 = tid + 256;
        ((uint4*)ws)[(u1 >> 5) * 34 + (u1 & 31)] = pre1;
    }
    __syncthreads();

    const int rb = rg * 32 + gid;

    float acc[2][4][4];
    #pragma unroll
    for (int mt = 0; mt < 2; mt++)
        #pragma unroll
        for (int nt = 0; nt < 4; nt++)
            #pragma unroll
            for (int q = 0; q < 4; q++) acc[mt][nt][q] = 0.f;

    for (int kc = 0; kc < 8; kc++) {
        uint4 pre0, pre1;
        if (kc + 1 < 8) {
            pre0 = Wi4[(kc + 1) * 512 + tid];
            pre1 = Wi4[(kc + 1) * 512 + tid + 256];
        }
        #pragma unroll
        for (int ks = 0; ks < 2; ks++) {
            int acol = kc * 16 + ks * 8 + ctg;
            unsigned a[2][4];
            #pragma unroll
            for (int mt = 0; mt < 2; mt++) {
                const unsigned* ap = xs + (rb + mt * 16) * XST + acol;
                a[mt][0] = ap[0];
                a[mt][1] = ap[8 * XST];
                a[mt][2] = ap[4];
                a[mt][3] = ap[8 * XST + 4];
            }
            #pragma unroll
            for (int nt = 0; nt < 4; nt++) {
                int bcol = cg * 32 + nt * 8 + gid;
                unsigned b0 = ws[(ks * 8 + ctg) * WST + bcol];
                unsigned b1 = ws[(ks * 8 + ctg + 4) * WST + bcol];
                mma8(acc[0][nt], a[0][0], a[0][1], a[0][2], a[0][3], b0, b1);
                mma8(acc[1][nt], a[1][0], a[1][1], a[1][2], a[1][3], b0, b1);
            }
        }
        __syncthreads();
        if (kc + 1 < 8) {
            ((uint4*)ws)[(tid >> 5) * 34 + (tid & 31)] = pre0;
            int u1 = tid + 256;
            ((uint4*)ws)[(u1 >> 5) * 34 + (u1 & 31)] = pre1;
            __syncthreads();
        }
    }

    float acc2[2][2][4];
    #pragma unroll
    for (int mt = 0; mt < 2; mt++) {
        int rA = rg * 32 + mt * 16 + gid;
        #pragma unroll
        for (int nt = 0; nt < 2; nt++) {
            int c0 = cg * 16 + nt * 8 + 2 * ctg;
            float bo0 = __ldg(&bo[c0]), bo1 = __ldg(&bo[c0 + 1]);
            acc2[mt][nt][0] = __uint_as_float(xs[rA * XST + 64 + c0]) + bo0;
            acc2[mt][nt][1] = __uint_as_float(xs[rA * XST + 64 + c0 + 1]) + bo1;
            acc2[mt][nt][2] = __uint_as_float(xs[(rA + 8) * XST + 64 + c0]) + bo0;
            acc2[mt][nt][3] = __uint_as_float(xs[(rA + 8) * XST + 64 + c0 + 1]) + bo1;
        }
    }
    __syncthreads();

    #pragma unroll
    for (int mt = 0; mt < 2; mt++) {
        int rA = rg * 32 + mt * 16 + gid;
        #pragma unroll
        for (int nt = 0; nt < 4; nt++) {
            int c0 = cg * 32 + nt * 8 + 2 * ctg;
            float bi0 = __ldg(&bi[c0]), bi1 = __ldg(&bi[c0 + 1]);
            xs[rA * XST + c0]           = f2tf(mishf(acc[mt][nt][0] + bi0));
            xs[rA * XST + c0 + 1]       = f2tf(mishf(acc[mt][nt][1] + bi1));
            xs[(rA + 8) * XST + c0]     = f2tf(mishf(acc[mt][nt][2] + bi0));
            xs[(rA + 8) * XST + c0 + 1] = f2tf(mishf(acc[mt][nt][3] + bi1));
        }
    }

    {
        uint4 preW = Wo4[tid];
        __syncthreads();
        ((uint4*)ws)[(tid >> 4) * 34 + (tid & 15)] = preW;
    }
    __syncthreads();

    for (int kc = 0; kc < 8; kc++) {
        uint4 pre;
        if (kc + 1 < 8) pre = Wo4[(kc + 1) * 256 + tid];
        #pragma unroll
        for (int ks = 0; ks < 2; ks++) {
            int acol = kc * 16 + ks * 8 + ctg;
            unsigned a[2][4];
            #pragma unroll
            for (int mt = 0; mt < 2; mt++) {
                const unsigned* ap = xs + (rb + mt * 16) * XST + acol;
                a[mt][0] = ap[0];
                a[mt][1] = ap[8 * XST];
                a[mt][2] = ap[4];
                a[mt][3] = ap[8 * XST + 4];
            }
            #pragma unroll
            for (int nt = 0; nt < 2; nt++) {
                int bcol = cg * 16 + nt * 8 + gid;
                unsigned b0 = ws[(ks * 8 + ctg) * WST + bcol];
                unsigned b1 = ws[(ks * 8 + ctg + 4) * WST + bcol];
                mma8(acc2[0][nt], a[0][0], a[0][1], a[0][2], a[0][3], b0, b1);
                mma8(acc2[1][nt], a[1][0], a[1][1], a[1][2], a[1][3], b0, b1);
            }
        }
        __syncthreads();
        if (kc + 1 < 8) {
            ((uint4*)ws)[(tid >> 4) * 34 + (tid & 15)] = pre;
            __syncthreads();
        }
    }

    #pragma unroll
    for (int mt = 0; mt < 2; mt++) {
        int rA = row0 + rg * 32 + mt * 16 + gid;
        #pragma unroll
        for (int nt = 0; nt < 2; nt++) {
            int c0 = cg * 16 + nt * 8 + 2 * ctg;
            if (rA < n)
                *(float2*)&hout[(size_t)rA * 64 + c0] = make_float2(acc2[mt][nt][0], acc2[mt][nt][1]);
            if (rA + 8 < n)
                *(float2*)&hout[(size_t)(rA + 8) * 64 + c0] = make_float2(acc2[mt][nt][2], acc2[mt][nt][3]);
        }
    }
}

// ---------------- readout ----------------
__global__ void bounds_kernel(const int* __restrict__ tok, int B) {
    if (threadIdx.x == 0) {
        int c = 0;
        g_bounds[0] = 0;
        for (int i = 0; i < B; i++) { c += tok[i]; g_bounds[i + 1] = c; }
    }
}

__global__ void segsum_kernel() {
    int b = blockIdx.x;
    int s = g_bounds[b], e = g_bounds[b + 1];
    int f = threadIdx.x & 63, g = threadIdx.x >> 6;
    float a = 0.f;
    for (int r = s + g; r < e; r += 4) a += g_hB[(size_t)r * 64 + f];
    __shared__ float red[256];
    red[threadIdx.x] = a;
    __syncthreads();
    if (g == 0) g_agg[b * 64 + f] = red[f] + red[64 + f] + red[128 + f] + red[192 + f];
}

__global__ void heads_kernel(const float* __restrict__ vWi, const float* __restrict__ vbi,
                             const float* __restrict__ vWo, const float* __restrict__ vbo,
                             const float* __restrict__ dWi, const float* __restrict__ dbi,
                             const float* __restrict__ dWo, const float* __restrict__ dbo,
                             float* __restrict__ out, int B)
{
    int b = blockIdx.x, o = threadIdx.x;
    __shared__ float a[64];
    __shared__ float red[64];
    a[o] = g_agg[b * 64 + o];
    __syncthreads();

    float t = vbi[o];
    for (int i = 0; i < 64; i++) t = fmaf(a[i], vWi[i * 64 + o], t);
    red[o] = mishf(t) * vWo[o];
    __syncthreads();
    for (int s = 32; s > 0; s >>= 1) {
        if (o < s) red[o] += red[o + s];
        __syncthreads();
    }
    if (o == 0) out[b] = red[0] + vbo[0];
    __syncthreads();

    t = dbi[o];
    for (int i = 0; i < 64; i++) t = fmaf(a[i], dWi[i * 64 + o], t);
    red[o] = mishf(t) * dWo[o];
    __syncthreads();
    for (int s = 32; s > 0; s >>= 1) {
        if (o < s) red[o] += red[o + s];
        __syncthreads();
    }
    if (o == 0) out[B + b] = red[0] + dbo[0];
}

// ---------------- host launch ----------------
static inline int smem_rel(int S, int A, int db) {
    return (64 * (S + 4) + (db ? 32 : 16) * (S + 8)) * 4 + 64 * A * 4;
}

extern "C" void kernel_launch(void* const* d_in, const int* in_sizes, int n_in,
                              void* d_out, int out_size)
{
    if (n_in < 29) return;
    const float* h0  = (const float*)d_in[0];
    const int*   a1  = (const int*)d_in[1];  int n1 = in_sizes[1];
    const int*   a2  = (const int*)d_in[2];  int n2 = in_sizes[2];
    const int*   a3  = (const int*)d_in[3];  int n3 = in_sizes[3];
    const int*   tok = (const int*)d_in[4];  int B  = in_sizes[4];
    const float* Wi1 = (const float*)d_in[5],  *bi1 = (const float*)d_in[6];
    const float* Wo1 = (const float*)d_in[7],  *bo1 = (const float*)d_in[8];
    const float* Wi2 = (const float*)d_in[9],  *bi2 = (const float*)d_in[10];
    const float* Wo2 = (const float*)d_in[11], *bo2 = (const float*)d_in[12];
    const float* Wi3 = (const float*)d_in[13], *bi3 = (const float*)d_in[14];
    const float* Wo3 = (const float*)d_in[15], *bo3 = (const float*)d_in[16];
    const float* uWi = (const float*)d_in[17], *ubi = (const float*)d_in[18];
    const float* uWo = (const float*)d_in[19], *ubo = (const float*)d_in[20];
    const float* vWi = (const float*)d_in[21], *vbi = (const float*)d_in[22];
    const float* vWo = (const float*)d_in[23], *vbo = (const float*)d_in[24];
    const float* dWi = (const float*)d_in[25], *dbi = (const float*)d_in[26];
    const float* dWo = (const float*)d_in[27], *dbo = (const float*)d_in[28];
    float* out = (float*)d_out;

    int N = in_sizes[0] / 64;
    int m1 = n1, m2 = n2 / 2, m3 = n3 / 3;
    (void)m1;
    int nb = (N + 1023) / 1024;

    const int SM1 = smem_rel(64, 1, 1);
    const int SM2 = smem_rel(128, 2, 0);
    const int SM3 = smem_rel(192, 3, 1);
    const int SMU = (64 * 132 + 16 * 136) * 4;

    cudaFuncSetAttribute(rel_kernel<64, 1, 1, 1, 1>,  cudaFuncAttributeMaxDynamicSharedMemorySize, SM1);
    cudaFuncSetAttribute(rel_kernel<128, 2, 2, 0, 0>, cudaFuncAttributeMaxDynamicSharedMemorySize, SM2);
    cudaFuncSetAttribute(rel_kernel<192, 3, 3, 1, 0>, cudaFuncAttributeMaxDynamicSharedMemorySize, SM3);
    cudaFuncSetAttribute(update_kernel,               cudaFuncAttributeMaxDynamicSharedMemorySize, SMU);

    // prologue: 5 launches; rel<192> is launch index 5 (ncu -s 5 -c 1 target)
    conv_all_kernel<<<(139264 + 255) / 256, 256>>>(Wi1, Wo1, Wi2, Wo2, Wi3, Wo3, uWi, uWo);
    zero_counts_kernel<<<(N + 255) / 256, 256>>>(N);
    count_all_kernel<<<1024, 256>>>(a1, n1, a2, n2, a3, n3);
    scan_local_kernel<<<nb, 1024>>>(N);
    scan_tops_kernel<<<1, 512>>>(nb, N);

    // layer 0 — rel kernels don't need the CSR
    rel_kernel<192, 3, 3, 1, 0><<<(m3 + 63) / 64, 256, SM3>>>(h0, 0, a3, m3, bi3, bo3, (long long)n2 * 64);

    scan_add_kernel<<<(N + 255) / 256, 256>>>(N);
    fill_all_kernel<<<1024, 256>>>(a2, n2, a3, n3);

    rel_kernel<128, 2, 2, 0, 0><<<(m2 + 63) / 64, 256, SM2>>>(h0, 0, a2, m2, bi2, bo2, 0LL);
    rel_kernel<64, 1, 1, 1, 1><<<(N + 63) / 64, 256, SM1>>>(h0, 0, nullptr, N, bi1, bo1, 0LL);
    agg_kernel<<<(N + 7) / 8, 256>>>(N);
    update_kernel<<<(N + 63) / 64, 256, SMU>>>(h0, 0, 1, N, ubi, ubo);

    // layer 1
    rel_kernel<192, 3, 3, 1, 0><<<(m3 + 63) / 64, 256, SM3>>>(h0, 1, a3, m3, bi3, bo3, (long long)n2 * 64);
    rel_kernel<128, 2, 2, 0, 0><<<(m2 + 63) / 64, 256, SM2>>>(h0, 1, a2, m2, bi2, bo2, 0LL);
    rel_kernel<64, 1, 1, 1, 1><<<(N + 63) / 64, 256, SM1>>>(h0, 1, nullptr, N, bi1, bo1, 0LL);
    agg_kernel<<<(N + 7) / 8, 256>>>(N);
    update_kernel<<<(N + 63) / 64, 256, SMU>>>(h0, 1, 2, N, ubi, ubo);

    // readout
    bounds_kernel<<<1, 32>>>(tok, B);
    segsum_kernel<<<B, 256>>>();
    heads_kernel<<<B, 64>>>(vWi, vbi, vWo, vbo, dWi, dbi, dWo, dbo, out, B);
}